// round 8
// baseline (speedup 1.0000x reference)
#include <cuda_runtime.h>
#include <cuda_bf16.h>
#include <cstdint>
#include <cstddef>

#define T_    2048
#define D_    256
#define NN_   2048
#define NH_   4
#define NL_   6
#define VOCAB_ 256
#define NHN_  (NH_ * NN_)
#define EPS_  1e-5f
#define TWO_PI_ 6.283185307179586f
#define INV_2PI_ 0.15915494309189535f

typedef __nv_bfloat16 bf16;
typedef __nv_bfloat162 bf162;

// ---------------- scratch (device globals; no allocations) ----------------
__device__ float g_x   [(size_t)T_ * D_];            // fp32 hidden
__device__ float g_pc  [(size_t)T_ * NN_];           // rope cos
__device__ float g_ps  [(size_t)T_ * NN_];           // rope sin
__device__ float g_xs  [(size_t)NH_ * T_ * NN_];     // x_sparse fp32 (gating)
__device__ float g_ykv [(size_t)NH_ * T_ * D_];      // yKV raw fp32
__device__ float g_part[(size_t)8 * T_ * D_];        // split-K partials

// bf16 hi/lo operand planes (all k-contiguous row-major)
__device__ bf16 xp_h[(size_t)T_ * D_],    xp_l[(size_t)T_ * D_];     // x [T][D]
__device__ bf16 xT_h[(size_t)D_ * T_],    xT_l[(size_t)D_ * T_];     // x^T [D][T]
__device__ bf16 qr_h[(size_t)NH_ * T_ * NN_], qr_l[(size_t)NH_ * T_ * NN_]; // qr / xy
__device__ bf16 sc_h[(size_t)NH_ * T_ * T_],  sc_l[(size_t)NH_ * T_ * T_];  // scores
__device__ bf16 yp_h[(size_t)NH_ * T_ * D_],  yp_l[(size_t)NH_ * T_ * D_];  // LN(yKV)
__device__ bf16 encT_h[(size_t)NH_ * NN_ * D_], encT_l[(size_t)NH_ * NN_ * D_];
__device__ bf16 envT_h[(size_t)NH_ * NN_ * D_], envT_l[(size_t)NH_ * NN_ * D_];
__device__ bf16 decT_h[(size_t)D_ * NHN_],     decT_l[(size_t)D_ * NHN_];
__device__ bf16 lmhT_h[(size_t)VOCAB_ * D_],   lmhT_l[(size_t)VOCAB_ * D_];

// ---------------- small helpers ----------------
__device__ __forceinline__ uint32_t smem_u32(const void* p) {
    return (uint32_t)__cvta_generic_to_shared(p);
}
__device__ __forceinline__ void cpa16(uint32_t dst, const void* src) {
    asm volatile("cp.async.ca.shared.global [%0], [%1], 16;\n" :: "r"(dst), "l"(src));
}
__device__ __forceinline__ void cpa_commit() { asm volatile("cp.async.commit_group;\n"); }
template <int N>
__device__ __forceinline__ void cpa_wait() { asm volatile("cp.async.wait_group %0;\n" :: "n"(N)); }

__device__ __forceinline__ void mma16(float* c,
                                      uint32_t a0, uint32_t a1, uint32_t a2, uint32_t a3,
                                      uint32_t b0, uint32_t b1) {
    asm volatile(
        "mma.sync.aligned.m16n8k16.row.col.f32.bf16.bf16.f32 "
        "{%0,%1,%2,%3},{%4,%5,%6,%7},{%8,%9},{%0,%1,%2,%3};"
        : "+f"(c[0]), "+f"(c[1]), "+f"(c[2]), "+f"(c[3])
        : "r"(a0), "r"(a1), "r"(a2), "r"(a3), "r"(b0), "r"(b1));
}

// split fp32 -> bf16 hi + bf16 lo (pairwise store)
__device__ __forceinline__ void st_split2(bf16* H, bf16* L, size_t idx, float v0, float v1) {
    bf16 h0 = __float2bfloat16(v0), h1 = __float2bfloat16(v1);
    float r0 = v0 - __bfloat162float(h0), r1 = v1 - __bfloat162float(h1);
    bf162 hv; hv.x = h0; hv.y = h1;
    bf162 lv; lv.x = __float2bfloat16(r0); lv.y = __float2bfloat16(r1);
    *reinterpret_cast<bf162*>(H + idx) = hv;
    *reinterpret_cast<bf162*>(L + idx) = lv;
}

// ---------------- block reduction over 256 threads ----------------
__device__ __forceinline__ float blk_sum256(float v) {
    __shared__ float sb[8];
    #pragma unroll
    for (int o = 16; o; o >>= 1) v += __shfl_xor_sync(0xffffffffu, v, o);
    int tid = threadIdx.x;
    if ((tid & 31) == 0) sb[tid >> 5] = v;
    __syncthreads();
    if (tid == 0) {
        float s = 0.f;
        #pragma unroll
        for (int i = 0; i < 8; i++) s += sb[i];
        sb[0] = s;
    }
    __syncthreads();
    float r = sb[0];
    __syncthreads();
    return r;
}

// ---------------- core GEMM: 128x128 tile, K-tiles of 16, bf16 3-term ----------------
// smem stage: 4 planes (Ah, Al, Bh, Bl), each [128 rows][12 u32] (8 kpairs + pad)
// 4-stage cp.async pipeline in dynamic smem (prefetch depth 3)
#define PLANE_U32 1536               // 128 * 12
#define PLANE_B   6144               // bytes
#define STAGE_U32 (4 * PLANE_U32)
#define STAGES    4
#define SMEM_DYN  (STAGES * STAGE_U32 * 4)   // 98304 bytes

__device__ __forceinline__ void gemm_bf16(
    const bf16* __restrict__ Agh, const bf16* __restrict__ Agl, int lda,
    const bf16* __restrict__ Bgh, const bf16* __restrict__ Bgl, int ldb,
    int K, uint32_t* sm, float (&acc)[4][4][4],
    int tid, int wm, int wn, int grp, int tig)
{
    const int NT  = K >> 4;
    const int row = tid >> 1;
    const int sub = tid & 1;
    const uint32_t dby = (uint32_t)(row * 12 + sub * 4) * 4u;
    const int go = sub * 8;  // element offset within k16

    auto issue = [&](int it) {
        int kb = it << 4;
        uint32_t sb = smem_u32(sm + (it & (STAGES - 1)) * STAGE_U32) + dby;
        cpa16(sb,               Agh + (size_t)row * lda + kb + go);
        cpa16(sb + PLANE_B,     Agl + (size_t)row * lda + kb + go);
        cpa16(sb + 2 * PLANE_B, Bgh + (size_t)row * ldb + kb + go);
        cpa16(sb + 3 * PLANE_B, Bgl + (size_t)row * ldb + kb + go);
        cpa_commit();
    };

    issue(0);
    if (1 < NT) issue(1);
    if (2 < NT) issue(2);

    for (int it = 0; it < NT; ++it) {
        if (it + 3 < NT) { issue(it + 3); cpa_wait<3>(); }
        else             { cpa_wait<0>(); }
        __syncthreads();
        const uint32_t* S  = sm + (it & (STAGES - 1)) * STAGE_U32;
        const uint32_t* Ah = S;
        const uint32_t* Al = S + PLANE_U32;
        const uint32_t* Bh = S + 2 * PLANE_U32;
        const uint32_t* Bl = S + 3 * PLANE_U32;

        uint32_t ah[4][4], al[4][4];
        #pragma unroll
        for (int mi = 0; mi < 4; mi++) {
            int r0 = (wm + mi * 16 + grp) * 12 + tig;
            ah[mi][0] = Ah[r0];      ah[mi][1] = Ah[r0 + 96];
            ah[mi][2] = Ah[r0 + 4];  ah[mi][3] = Ah[r0 + 100];
            al[mi][0] = Al[r0];      al[mi][1] = Al[r0 + 96];
            al[mi][2] = Al[r0 + 4];  al[mi][3] = Al[r0 + 100];
        }
        #pragma unroll
        for (int ni = 0; ni < 4; ni++) {
            int c0 = (wn + ni * 8 + grp) * 12 + tig;
            uint32_t bh0 = Bh[c0], bh1 = Bh[c0 + 4];
            uint32_t bl0 = Bl[c0], bl1 = Bl[c0 + 4];
            #pragma unroll
            for (int mi = 0; mi < 4; mi++) {
                mma16(acc[mi][ni], ah[mi][0], ah[mi][1], ah[mi][2], ah[mi][3], bh0, bh1);
                mma16(acc[mi][ni], al[mi][0], al[mi][1], al[mi][2], al[mi][3], bh0, bh1);
                mma16(acc[mi][ni], ah[mi][0], ah[mi][1], ah[mi][2], ah[mi][3], bl0, bl1);
            }
        }
        __syncthreads();
    }
}

#define WARP_IDS                                   \
    const int tid = threadIdx.x;                   \
    const int lane = tid & 31, warp = tid >> 5;    \
    const int grp = lane >> 2, tig = lane & 3;     \
    const int wm = (warp >> 2) * 64, wn = (warp & 3) * 32;

#define ZERO_ACC float acc[4][4][4];               \
    _Pragma("unroll") for (int i = 0; i < 4; i++)  \
    _Pragma("unroll") for (int j = 0; j < 4; j++)  \
    _Pragma("unroll") for (int r = 0; r < 4; r++) acc[i][j][r] = 0.f;

// plain fp32 store of the 128x128 tile
__device__ __forceinline__ void store_plain(float* __restrict__ Cb, int ldc,
                                            int t_blk, int c_blk, const float (&acc)[4][4][4],
                                            int wm, int wn, int grp, int tig) {
    #pragma unroll
    for (int mi = 0; mi < 4; mi++)
        #pragma unroll
        for (int ni = 0; ni < 4; ni++) {
            int col = c_blk + wn + ni * 8 + 2 * tig;
            #pragma unroll
            for (int h = 0; h < 2; h++) {
                int row = t_blk + wm + mi * 16 + grp + 8 * h;
                float2 v = make_float2(acc[mi][ni][2 * h], acc[mi][ni][2 * h + 1]);
                *reinterpret_cast<float2*>(&Cb[(size_t)row * ldc + col]) = v;
            }
        }
}

// ---------------- prep: transpose fp32 [R][C] -> bf16 hi/lo planes [C][R] ----------------
__global__ void k_tsplit(const float* __restrict__ src, bf16* __restrict__ H,
                         bf16* __restrict__ L, int R, int C) {
    __shared__ float s[32][33];
    size_t zo  = (size_t)blockIdx.z * R * C;
    int c0 = blockIdx.x * 32, r0 = blockIdx.y * 32;
    #pragma unroll
    for (int i = 0; i < 4; i++) {
        int r = r0 + threadIdx.y + i * 8;
        s[threadIdx.y + i * 8][threadIdx.x] = src[zo + (size_t)r * C + c0 + threadIdx.x];
    }
    __syncthreads();
    size_t zo2 = (size_t)blockIdx.z * C * R;
    #pragma unroll
    for (int i = 0; i < 4; i++) {
        int c = c0 + threadIdx.y + i * 8;
        float v = s[threadIdx.x][threadIdx.y + i * 8];
        bf16 h = __float2bfloat16(v);
        size_t o = zo2 + (size_t)c * R + r0 + threadIdx.x;
        H[o] = h;
        L[o] = __float2bfloat16(v - __bfloat162float(h));
    }
}

// ---------------- RoPE cos/sin tables ----------------
__global__ void k_rope_tab() {
    int t = blockIdx.x;
    for (int n = threadIdx.x; n < NN_; n += 256) {
        float q    = (float)(n & ~1);
        float freq = exp2f(-q * (1.0f / 128.0f)) * INV_2PI_;   // THETA = 2^16
        float ph   = fmodf((float)t * freq, 1.0f) * TWO_PI_;
        float s, c;
        sincosf(ph, &s, &c);
        g_pc[(size_t)t * NN_ + n] = c;
        g_ps[(size_t)t * NN_ + n] = s;
    }
}

// ---------------- x = LN(embed[idx]); write fp32 + planes + transposed planes ----------------
__global__ void k_embed_ln(const int* __restrict__ idx, const float* __restrict__ embed) {
    int t = blockIdx.x, d = threadIdx.x;
    float v   = embed[(size_t)idx[t] * D_ + d];
    float m   = blk_sum256(v) * (1.0f / D_);
    float dv  = v - m;
    float var = blk_sum256(dv * dv) * (1.0f / D_);
    float x = dv * rsqrtf(var + EPS_);
    size_t o = (size_t)t * D_ + d;
    g_x[o] = x;
    bf16 h = __float2bfloat16(x);
    bf16 l = __float2bfloat16(x - __bfloat162float(h));
    xp_h[o] = h; xp_l[o] = l;
    size_t ot = (size_t)d * T_ + t;
    xT_h[ot] = h; xT_l[ot] = l;
}

// ---------------- enc GEMM: MODE 1: xs=relu(x@enc), qr=rope(xs)
// ----------------           MODE 4: xy = relu(yKV@encv) * xs (into qr planes)
template <int MODE>
__global__ void __launch_bounds__(256, 2) k_enc() {
    extern __shared__ uint32_t smd[];
    WARP_IDS
    const int h = blockIdx.z;
    const int t_blk = blockIdx.y * 128, n_blk = blockIdx.x * 128;
    const bf16 *Agh, *Agl, *Bgh, *Bgl;
    if (MODE == 1) {
        Agh = xp_h + (size_t)t_blk * D_;
        Agl = xp_l + (size_t)t_blk * D_;
        Bgh = encT_h + ((size_t)h * NN_ + n_blk) * D_;
        Bgl = encT_l + ((size_t)h * NN_ + n_blk) * D_;
    } else {
        Agh = yp_h + ((size_t)h * T_ + t_blk) * D_;
        Agl = yp_l + ((size_t)h * T_ + t_blk) * D_;
        Bgh = envT_h + ((size_t)h * NN_ + n_blk) * D_;
        Bgl = envT_l + ((size_t)h * NN_ + n_blk) * D_;
    }
    ZERO_ACC
    gemm_bf16(Agh, Agl, D_, Bgh, Bgl, D_, D_, smd, acc, tid, wm, wn, grp, tig);

    const size_t hbase = (size_t)h * T_ * NN_;
    #pragma unroll
    for (int mi = 0; mi < 4; mi++)
        #pragma unroll
        for (int ni = 0; ni < 4; ni++) {
            int C0 = n_blk + wn + ni * 8 + 2 * tig;
            #pragma unroll
            for (int hh = 0; hh < 2; hh++) {
                int t = t_blk + wm + mi * 16 + grp + 8 * hh;
                float v0 = fmaxf(acc[mi][ni][2 * hh], 0.f);
                float v1 = fmaxf(acc[mi][ni][2 * hh + 1], 0.f);
                size_t rb = hbase + (size_t)t * NN_ + C0;
                if (MODE == 1) {
                    *reinterpret_cast<float2*>(&g_xs[rb]) = make_float2(v0, v1);
                    float2 pc = *reinterpret_cast<const float2*>(&g_pc[(size_t)t * NN_ + C0]);
                    float2 ps = *reinterpret_cast<const float2*>(&g_ps[(size_t)t * NN_ + C0]);
                    float q0 = v0 * pc.x - v1 * ps.x;
                    float q1 = v1 * pc.y + v0 * ps.y;
                    st_split2(qr_h, qr_l, rb, q0, q1);
                } else {
                    float2 xs = *reinterpret_cast<const float2*>(&g_xs[rb]);
                    st_split2(qr_h, qr_l, rb, v0 * xs.x, v1 * xs.y);
                }
            }
        }
}

// ---------------- scores = tril(qr @ qr^T, k=-1) into sc planes ----------------
__global__ void __launch_bounds__(256, 2) k_scores() {
    int bx = blockIdx.x, by = blockIdx.y, hz = blockIdx.z;
    if (bx > by) return;
    extern __shared__ uint32_t smd[];
    WARP_IDS
    const bf16* Agh = qr_h + ((size_t)hz * T_ + by * 128) * NN_;
    const bf16* Agl = qr_l + ((size_t)hz * T_ + by * 128) * NN_;
    const bf16* Bgh = qr_h + ((size_t)hz * T_ + bx * 128) * NN_;
    const bf16* Bgl = qr_l + ((size_t)hz * T_ + bx * 128) * NN_;
    ZERO_ACC
    gemm_bf16(Agh, Agl, NN_, Bgh, Bgl, NN_, NN_, smd, acc, tid, wm, wn, grp, tig);

    const size_t hbase = (size_t)hz * T_ * T_;
    int t_blk = by * 128, u_blk = bx * 128;
    if (bx != by) {
        #pragma unroll
        for (int mi = 0; mi < 4; mi++)
            #pragma unroll
            for (int ni = 0; ni < 4; ni++) {
                int C0 = u_blk + wn + ni * 8 + 2 * tig;
                #pragma unroll
                for (int h2 = 0; h2 < 2; h2++) {
                    int t = t_blk + wm + mi * 16 + grp + 8 * h2;
                    st_split2(sc_h, sc_l, hbase + (size_t)t * T_ + C0,
                              acc[mi][ni][2 * h2], acc[mi][ni][2 * h2 + 1]);
                }
            }
    } else {
        #pragma unroll
        for (int mi = 0; mi < 4; mi++)
            #pragma unroll
            for (int ni = 0; ni < 4; ni++) {
                int C0 = u_blk + wn + ni * 8 + 2 * tig;
                #pragma unroll
                for (int h2 = 0; h2 < 2; h2++) {
                    int t = t_blk + wm + mi * 16 + grp + 8 * h2;
                    float v0 = (C0     < t) ? acc[mi][ni][2 * h2]     : 0.f;
                    float v1 = (C0 + 1 < t) ? acc[mi][ni][2 * h2 + 1] : 0.f;
                    st_split2(sc_h, sc_l, hbase + (size_t)t * T_ + C0, v0, v1);
                }
            }
    }
}

// ---------------- yKV_raw = scores @ x (K limited by causality) ----------------
__global__ void __launch_bounds__(256, 2) k_ykv() {
    extern __shared__ uint32_t smd[];
    WARP_IDS
    const int h = blockIdx.z;
    const int Kend = (blockIdx.y + 1) * 128;
    const bf16* Agh = sc_h + ((size_t)h * T_ + blockIdx.y * 128) * T_;
    const bf16* Agl = sc_l + ((size_t)h * T_ + blockIdx.y * 128) * T_;
    const bf16* Bgh = xT_h + (size_t)blockIdx.x * 128 * T_;
    const bf16* Bgl = xT_l + (size_t)blockIdx.x * 128 * T_;
    ZERO_ACC
    gemm_bf16(Agh, Agl, T_, Bgh, Bgl, T_, Kend, smd, acc, tid, wm, wn, grp, tig);
    store_plain(g_ykv + (size_t)h * T_ * D_, D_, blockIdx.y * 128, blockIdx.x * 128,
                acc, wm, wn, grp, tig);
}

// ---------------- LN(yKV) -> planes ----------------
__global__ void k_ln_ykv() {
    size_t r = blockIdx.x;
    int d = threadIdx.x;
    float v   = g_ykv[r * D_ + d];
    float m   = blk_sum256(v) * (1.0f / D_);
    float dv  = v - m;
    float var = blk_sum256(dv * dv) * (1.0f / D_);
    float y = dv * rsqrtf(var + EPS_);
    bf16 h = __float2bfloat16(y);
    yp_h[r * D_ + d] = h;
    yp_l[r * D_ + d] = __float2bfloat16(y - __bfloat162float(h));
}

// ---------------- decoder GEMM, split-K=8 ----------------
__global__ void __launch_bounds__(256, 2) k_dec() {
    extern __shared__ uint32_t smd[];
    WARP_IDS
    const int seg = blockIdx.z;
    const int h = seg >> 1;
    const int colb = (seg & 1) * 1024;
    const int t_blk = blockIdx.y * 128, c_blk = blockIdx.x * 128;
    const bf16* Agh = qr_h + ((size_t)h * T_ + t_blk) * NN_ + colb;
    const bf16* Agl = qr_l + ((size_t)h * T_ + t_blk) * NN_ + colb;
    const bf16* Bgh = decT_h + (size_t)c_blk * NHN_ + seg * 1024;
    const bf16* Bgl = decT_l + (size_t)c_blk * NHN_ + seg * 1024;
    ZERO_ACC
    gemm_bf16(Agh, Agl, NN_, Bgh, Bgl, NHN_, 1024, smd, acc, tid, wm, wn, grp, tig);
    store_plain(g_part + (size_t)seg * T_ * D_, D_, t_blk, c_blk, acc, wm, wn, grp, tig);
}

// ---------------- x = LN(x + LN(sum_partials)); refresh planes ----------------
__global__ void k_ln2() {
    int t = blockIdx.x, d = threadIdx.x;
    size_t o = (size_t)t * D_ + d;
    float y = 0.f;
    #pragma unroll
    for (int s = 0; s < 8; s++) y += g_part[(size_t)s * T_ * D_ + o];
    float m1 = blk_sum256(y) * (1.0f / D_);
    float dy = y - m1;
    float v1 = blk_sum256(dy * dy) * (1.0f / D_);
    float u  = dy * rsqrtf(v1 + EPS_);
    float w  = g_x[o] + u;
    float m2 = blk_sum256(w) * (1.0f / D_);
    float dw = w - m2;
    float v2 = blk_sum256(dw * dw) * (1.0f / D_);
    float x  = dw * rsqrtf(v2 + EPS_);
    g_x[o] = x;
    bf16 h = __float2bfloat16(x);
    bf16 l = __float2bfloat16(x - __bfloat162float(h));
    xp_h[o] = h; xp_l[o] = l;
    size_t ot = (size_t)d * T_ + t;
    xT_h[ot] = h; xT_l[ot] = l;
}

// ---------------- logits = x @ lm_head ----------------
__global__ void __launch_bounds__(256, 2) k_logits(float* __restrict__ out) {
    extern __shared__ uint32_t smd[];
    WARP_IDS
    const int t_blk = blockIdx.y * 128, c_blk = blockIdx.x * 128;
    const bf16* Agh = xp_h + (size_t)t_blk * D_;
    const bf16* Agl = xp_l + (size_t)t_blk * D_;
    const bf16* Bgh = lmhT_h + (size_t)c_blk * D_;
    const bf16* Bgl = lmhT_l + (size_t)c_blk * D_;
    ZERO_ACC
    gemm_bf16(Agh, Agl, D_, Bgh, Bgl, D_, D_, smd, acc, tid, wm, wn, grp, tig);
    store_plain(out, VOCAB_, t_blk, c_blk, acc, wm, wn, grp, tig);
}

// ---------------- host launch ----------------
extern "C" void kernel_launch(void* const* d_in, const int* in_sizes, int n_in,
                              void* d_out, int out_size) {
    (void)in_sizes; (void)n_in; (void)out_size;
    const int*   idx   = (const int*)d_in[0];
    const float* embed = (const float*)d_in[1];
    const float* enc   = (const float*)d_in[2];
    const float* encv  = (const float*)d_in[3];
    const float* dec   = (const float*)d_in[4];
    const float* lmh   = (const float*)d_in[5];
    float* out = (float*)d_out;

    // opt-in dynamic smem for the GEMM kernels (idempotent; no allocation)
    cudaFuncSetAttribute(k_enc<1>, cudaFuncAttributeMaxDynamicSharedMemorySize, SMEM_DYN);
    cudaFuncSetAttribute(k_enc<4>, cudaFuncAttributeMaxDynamicSharedMemorySize, SMEM_DYN);
    cudaFuncSetAttribute(k_scores, cudaFuncAttributeMaxDynamicSharedMemorySize, SMEM_DYN);
    cudaFuncSetAttribute(k_ykv,    cudaFuncAttributeMaxDynamicSharedMemorySize, SMEM_DYN);
    cudaFuncSetAttribute(k_dec,    cudaFuncAttributeMaxDynamicSharedMemorySize, SMEM_DYN);
    cudaFuncSetAttribute(k_logits, cudaFuncAttributeMaxDynamicSharedMemorySize, SMEM_DYN);

    bf16 *p_encT_h, *p_encT_l, *p_envT_h, *p_envT_l, *p_decT_h, *p_decT_l, *p_lmhT_h, *p_lmhT_l;
    cudaGetSymbolAddress((void**)&p_encT_h, encT_h);
    cudaGetSymbolAddress((void**)&p_encT_l, encT_l);
    cudaGetSymbolAddress((void**)&p_envT_h, envT_h);
    cudaGetSymbolAddress((void**)&p_envT_l, envT_l);
    cudaGetSymbolAddress((void**)&p_decT_h, decT_h);
    cudaGetSymbolAddress((void**)&p_decT_l, decT_l);
    cudaGetSymbolAddress((void**)&p_lmhT_h, lmhT_h);
    cudaGetSymbolAddress((void**)&p_lmhT_l, lmhT_l);

    dim3 tb(32, 8);
    k_rope_tab<<<T_, 256>>>();
    k_tsplit<<<dim3(NN_ / 32, D_ / 32, NH_), tb>>>(enc,  p_encT_h, p_encT_l, D_, NN_);
    k_tsplit<<<dim3(NN_ / 32, D_ / 32, NH_), tb>>>(encv, p_envT_h, p_envT_l, D_, NN_);
    k_tsplit<<<dim3(D_ / 32, NHN_ / 32, 1), tb>>>(dec,  p_decT_h, p_decT_l, NHN_, D_);
    k_tsplit<<<dim3(VOCAB_ / 32, D_ / 32, 1), tb>>>(lmh, p_lmhT_h, p_lmhT_l, D_, VOCAB_);
    k_embed_ln<<<T_, 256>>>(idx, embed);

    for (int l = 0; l < NL_; ++l) {
        k_enc<1><<<dim3(16, 16, NH_), 256, SMEM_DYN>>>();
        k_scores<<<dim3(16, 16, NH_), 256, SMEM_DYN>>>();
        k_ykv<<<dim3(2, 16, NH_), 256, SMEM_DYN>>>();
        k_ln_ykv<<<NH_ * T_, 256>>>();
        k_enc<4><<<dim3(16, 16, NH_), 256, SMEM_DYN>>>();
        k_dec<<<dim3(2, 16, 8), 256, SMEM_DYN>>>();
        k_ln2<<<T_, 256>>>();
    }
    k_logits<<<dim3(2, 16, 1), 256, SMEM_DYN>>>(out);
}

// round 13
// speedup vs baseline: 1.1053x; 1.1053x over previous
#include <cuda_runtime.h>
#include <cuda_bf16.h>
#include <cstdint>
#include <cstddef>

#define T_    2048
#define D_    256
#define NN_   2048
#define NH_   4
#define NL_   6
#define VOCAB_ 256
#define NHN_  (NH_ * NN_)
#define EPS_  1e-5f
#define TWO_PI_ 6.283185307179586f
#define INV_2PI_ 0.15915494309189535f

typedef __nv_bfloat16 bf16;
typedef __nv_bfloat162 bf162;

// ---------------- scratch (device globals; no allocations) ----------------
__device__ float g_x   [(size_t)T_ * D_];
__device__ float g_pc  [(size_t)T_ * NN_];
__device__ float g_ps  [(size_t)T_ * NN_];
__device__ float g_xs  [(size_t)NH_ * T_ * NN_];
__device__ float g_ykv [(size_t)NH_ * T_ * D_];
__device__ float g_part[(size_t)8 * T_ * D_];

__device__ bf16 xp_h[(size_t)T_ * D_],    xp_l[(size_t)T_ * D_];
__device__ bf16 xT_h[(size_t)D_ * T_],    xT_l[(size_t)D_ * T_];
__device__ bf16 qr_h[(size_t)NH_ * T_ * NN_], qr_l[(size_t)NH_ * T_ * NN_];
__device__ bf16 sc_h[(size_t)NH_ * T_ * T_],  sc_l[(size_t)NH_ * T_ * T_];
__device__ bf16 yp_h[(size_t)NH_ * T_ * D_],  yp_l[(size_t)NH_ * T_ * D_];
__device__ bf16 encT_h[(size_t)NH_ * NN_ * D_], encT_l[(size_t)NH_ * NN_ * D_];
__device__ bf16 envT_h[(size_t)NH_ * NN_ * D_], envT_l[(size_t)NH_ * NN_ * D_];
__device__ bf16 decT_h[(size_t)D_ * NHN_],     decT_l[(size_t)D_ * NHN_];
__device__ bf16 lmhT_h[(size_t)VOCAB_ * D_],   lmhT_l[(size_t)VOCAB_ * D_];

// ---------------- small helpers ----------------
__device__ __forceinline__ uint32_t smem_u32(const void* p) {
    return (uint32_t)__cvta_generic_to_shared(p);
}
__device__ __forceinline__ void cpa16(uint32_t dst, const void* src) {
    asm volatile("cp.async.ca.shared.global [%0], [%1], 16;\n" :: "r"(dst), "l"(src));
}
__device__ __forceinline__ void cpa_commit() { asm volatile("cp.async.commit_group;\n"); }
template <int N>
__device__ __forceinline__ void cpa_wait() { asm volatile("cp.async.wait_group %0;\n" :: "n"(N)); }

__device__ __forceinline__ void mma16(float* c,
                                      uint32_t a0, uint32_t a1, uint32_t a2, uint32_t a3,
                                      uint32_t b0, uint32_t b1) {
    asm volatile(
        "mma.sync.aligned.m16n8k16.row.col.f32.bf16.bf16.f32 "
        "{%0,%1,%2,%3},{%4,%5,%6,%7},{%8,%9},{%0,%1,%2,%3};"
        : "+f"(c[0]), "+f"(c[1]), "+f"(c[2]), "+f"(c[3])
        : "r"(a0), "r"(a1), "r"(a2), "r"(a3), "r"(b0), "r"(b1));
}

// split fp32 -> bf16 hi + bf16 lo (pairwise store)
__device__ __forceinline__ void st_split2(bf16* H, bf16* L, size_t idx, float v0, float v1) {
    bf16 h0 = __float2bfloat16(v0), h1 = __float2bfloat16(v1);
    float r0 = v0 - __bfloat162float(h0), r1 = v1 - __bfloat162float(h1);
    bf162 hv; hv.x = h0; hv.y = h1;
    bf162 lv; lv.x = __float2bfloat16(r0); lv.y = __float2bfloat16(r1);
    *reinterpret_cast<bf162*>(H + idx) = hv;
    *reinterpret_cast<bf162*>(L + idx) = lv;
}

// ---------------- block reduction over 256 threads ----------------
__device__ __forceinline__ float blk_sum256(float v) {
    __shared__ float sb[8];
    #pragma unroll
    for (int o = 16; o; o >>= 1) v += __shfl_xor_sync(0xffffffffu, v, o);
    int tid = threadIdx.x;
    if ((tid & 31) == 0) sb[tid >> 5] = v;
    __syncthreads();
    if (tid == 0) {
        float s = 0.f;
        #pragma unroll
        for (int i = 0; i < 8; i++) s += sb[i];
        sb[0] = s;
    }
    __syncthreads();
    float r = sb[0];
    __syncthreads();
    return r;
}

// ---------------- core GEMM: 128x128 tile, K-tiles of 16, bf16 3-term ----------------
// smem stage: 4 planes (Ah, Al, Bh, Bl), each [128 rows][12 u32] (8 kpairs + pad)
// 3-stage cp.async pipeline, ONE barrier per iteration:
//   wait(own groups) -> __syncthreads (all groups in) -> compute -> issue(it+2)
#define PLANE_U32 1536               // 128 * 12
#define PLANE_B   6144               // bytes
#define STAGE_U32 (4 * PLANE_U32)
#define STAGES    3
#define SMEM_DYN  (STAGES * STAGE_U32 * 4)   // 73728 bytes

__device__ __forceinline__ void gemm_bf16(
    const bf16* __restrict__ Agh, const bf16* __restrict__ Agl, int lda,
    const bf16* __restrict__ Bgh, const bf16* __restrict__ Bgl, int ldb,
    int K, uint32_t* sm, float (&acc)[4][4][4],
    int tid, int wm, int wn, int grp, int tig)
{
    const int NT  = K >> 4;
    const int row = tid >> 1;
    const int sub = tid & 1;
    const uint32_t dby = (uint32_t)(row * 12 + sub * 4) * 4u;
    const int go = sub * 8;  // element offset within k16

    auto issue = [&](int it) {
        int kb = it << 4;
        uint32_t sb = smem_u32(sm + (uint32_t)(it % STAGES) * STAGE_U32) + dby;
        cpa16(sb,               Agh + (size_t)row * lda + kb + go);
        cpa16(sb + PLANE_B,     Agl + (size_t)row * lda + kb + go);
        cpa16(sb + 2 * PLANE_B, Bgh + (size_t)row * ldb + kb + go);
        cpa16(sb + 3 * PLANE_B, Bgl + (size_t)row * ldb + kb + go);
        cpa_commit();
    };

    issue(0);
    issue(1);

    for (int it = 0; it < NT; ++it) {
        // complete my own group(it); groups {it, it+1} may be pending
        if (it + 1 < NT) cpa_wait<1>();
        else             cpa_wait<0>();
        __syncthreads();   // => every thread's group(it) complete; all compute(it-1) done

        const uint32_t* S  = sm + (uint32_t)(it % STAGES) * STAGE_U32;
        const uint32_t* Ah = S;
        const uint32_t* Al = S + PLANE_U32;
        const uint32_t* Bh = S + 2 * PLANE_U32;
        const uint32_t* Bl = S + 3 * PLANE_U32;

        uint32_t ah[4][4], al[4][4];
        #pragma unroll
        for (int mi = 0; mi < 4; mi++) {
            int r0 = (wm + mi * 16 + grp) * 12 + tig;
            ah[mi][0] = Ah[r0];      ah[mi][1] = Ah[r0 + 96];
            ah[mi][2] = Ah[r0 + 4];  ah[mi][3] = Ah[r0 + 100];
            al[mi][0] = Al[r0];      al[mi][1] = Al[r0 + 96];
            al[mi][2] = Al[r0 + 4];  al[mi][3] = Al[r0 + 100];
        }
        #pragma unroll
        for (int ni = 0; ni < 4; ni++) {
            int c0 = (wn + ni * 8 + grp) * 12 + tig;
            uint32_t bh0 = Bh[c0], bh1 = Bh[c0 + 4];
            uint32_t bl0 = Bl[c0], bl1 = Bl[c0 + 4];
            #pragma unroll
            for (int mi = 0; mi < 4; mi++) {
                mma16(acc[mi][ni], ah[mi][0], ah[mi][1], ah[mi][2], ah[mi][3], bh0, bh1);
                mma16(acc[mi][ni], al[mi][0], al[mi][1], al[mi][2], al[mi][3], bh0, bh1);
                mma16(acc[mi][ni], ah[mi][0], ah[mi][1], ah[mi][2], ah[mi][3], bl0, bl1);
            }
        }

        // overwrite stage (it+2)%3 == (it-1)%3: all warps passed barrier(it),
        // which postdates every warp's compute(it-1). Safe.
        if (it + 2 < NT) issue(it + 2);
    }
    __syncthreads();   // protect smem before epilogue reuse / kernel end
}

#define WARP_IDS                                   \
    const int tid = threadIdx.x;                   \
    const int lane = tid & 31, warp = tid >> 5;    \
    const int grp = lane >> 2, tig = lane & 3;     \
    const int wm = (warp >> 2) * 64, wn = (warp & 3) * 32;

#define ZERO_ACC float acc[4][4][4];               \
    _Pragma("unroll") for (int i = 0; i < 4; i++)  \
    _Pragma("unroll") for (int j = 0; j < 4; j++)  \
    _Pragma("unroll") for (int r = 0; r < 4; r++) acc[i][j][r] = 0.f;

// plain fp32 store of the 128x128 tile
__device__ __forceinline__ void store_plain(float* __restrict__ Cb, int ldc,
                                            int t_blk, int c_blk, const float (&acc)[4][4][4],
                                            int wm, int wn, int grp, int tig) {
    #pragma unroll
    for (int mi = 0; mi < 4; mi++)
        #pragma unroll
        for (int ni = 0; ni < 4; ni++) {
            int col = c_blk + wn + ni * 8 + 2 * tig;
            #pragma unroll
            for (int h = 0; h < 2; h++) {
                int row = t_blk + wm + mi * 16 + grp + 8 * h;
                float2 v = make_float2(acc[mi][ni][2 * h], acc[mi][ni][2 * h + 1]);
                *reinterpret_cast<float2*>(&Cb[(size_t)row * ldc + col]) = v;
            }
        }
}

// ---------------- prep: transpose fp32 [R][C] -> bf16 hi/lo planes [C][R] ----------------
__global__ void k_tsplit(const float* __restrict__ src, bf16* __restrict__ H,
                         bf16* __restrict__ L, int R, int C) {
    __shared__ float s[32][33];
    size_t zo  = (size_t)blockIdx.z * R * C;
    int c0 = blockIdx.x * 32, r0 = blockIdx.y * 32;
    #pragma unroll
    for (int i = 0; i < 4; i++) {
        int r = r0 + threadIdx.y + i * 8;
        s[threadIdx.y + i * 8][threadIdx.x] = src[zo + (size_t)r * C + c0 + threadIdx.x];
    }
    __syncthreads();
    size_t zo2 = (size_t)blockIdx.z * C * R;
    #pragma unroll
    for (int i = 0; i < 4; i++) {
        int c = c0 + threadIdx.y + i * 8;
        float v = s[threadIdx.x][threadIdx.y + i * 8];
        bf16 h = __float2bfloat16(v);
        size_t o = zo2 + (size_t)c * R + r0 + threadIdx.x;
        H[o] = h;
        L[o] = __float2bfloat16(v - __bfloat162float(h));
    }
}

// ---------------- RoPE cos/sin tables ----------------
__global__ void k_rope_tab() {
    int t = blockIdx.x;
    for (int n = threadIdx.x; n < NN_; n += 256) {
        float q    = (float)(n & ~1);
        float freq = exp2f(-q * (1.0f / 128.0f)) * INV_2PI_;   // THETA = 2^16
        float ph   = fmodf((float)t * freq, 1.0f) * TWO_PI_;
        float s, c;
        sincosf(ph, &s, &c);
        g_pc[(size_t)t * NN_ + n] = c;
        g_ps[(size_t)t * NN_ + n] = s;
    }
}

// ---------------- x = LN(embed[idx]); write fp32 + planes + transposed planes ----------------
__global__ void k_embed_ln(const int* __restrict__ idx, const float* __restrict__ embed) {
    int t = blockIdx.x, d = threadIdx.x;
    float v   = embed[(size_t)idx[t] * D_ + d];
    float m   = blk_sum256(v) * (1.0f / D_);
    float dv  = v - m;
    float var = blk_sum256(dv * dv) * (1.0f / D_);
    float x = dv * rsqrtf(var + EPS_);
    size_t o = (size_t)t * D_ + d;
    g_x[o] = x;
    bf16 h = __float2bfloat16(x);
    bf16 l = __float2bfloat16(x - __bfloat162float(h));
    xp_h[o] = h; xp_l[o] = l;
    size_t ot = (size_t)d * T_ + t;
    xT_h[ot] = h; xT_l[ot] = l;
}

// ---------------- enc GEMM: MODE 1: xs=relu(x@enc), qr=rope(xs)
// ----------------           MODE 4: xy = relu(yKV@encv) * xs (into qr planes)
template <int MODE>
__global__ void __launch_bounds__(256, 2) k_enc() {
    extern __shared__ uint32_t smd[];
    WARP_IDS
    const int h = blockIdx.z;
    const int t_blk = blockIdx.y * 128, n_blk = blockIdx.x * 128;
    const bf16 *Agh, *Agl, *Bgh, *Bgl;
    if (MODE == 1) {
        Agh = xp_h + (size_t)t_blk * D_;
        Agl = xp_l + (size_t)t_blk * D_;
        Bgh = encT_h + ((size_t)h * NN_ + n_blk) * D_;
        Bgl = encT_l + ((size_t)h * NN_ + n_blk) * D_;
    } else {
        Agh = yp_h + ((size_t)h * T_ + t_blk) * D_;
        Agl = yp_l + ((size_t)h * T_ + t_blk) * D_;
        Bgh = envT_h + ((size_t)h * NN_ + n_blk) * D_;
        Bgl = envT_l + ((size_t)h * NN_ + n_blk) * D_;
    }
    ZERO_ACC
    gemm_bf16(Agh, Agl, D_, Bgh, Bgl, D_, D_, smd, acc, tid, wm, wn, grp, tig);

    const size_t hbase = (size_t)h * T_ * NN_;
    #pragma unroll
    for (int mi = 0; mi < 4; mi++)
        #pragma unroll
        for (int ni = 0; ni < 4; ni++) {
            int C0 = n_blk + wn + ni * 8 + 2 * tig;
            #pragma unroll
            for (int hh = 0; hh < 2; hh++) {
                int t = t_blk + wm + mi * 16 + grp + 8 * hh;
                float v0 = fmaxf(acc[mi][ni][2 * hh], 0.f);
                float v1 = fmaxf(acc[mi][ni][2 * hh + 1], 0.f);
                size_t rb = hbase + (size_t)t * NN_ + C0;
                if (MODE == 1) {
                    *reinterpret_cast<float2*>(&g_xs[rb]) = make_float2(v0, v1);
                    float2 pc = *reinterpret_cast<const float2*>(&g_pc[(size_t)t * NN_ + C0]);
                    float2 ps = *reinterpret_cast<const float2*>(&g_ps[(size_t)t * NN_ + C0]);
                    float q0 = v0 * pc.x - v1 * ps.x;
                    float q1 = v1 * pc.y + v0 * ps.y;
                    st_split2(qr_h, qr_l, rb, q0, q1);
                } else {
                    float2 xs = *reinterpret_cast<const float2*>(&g_xs[rb]);
                    st_split2(qr_h, qr_l, rb, v0 * xs.x, v1 * xs.y);
                }
            }
        }
}

// ---------------- scores = tril(qr @ qr^T, k=-1) into sc planes ----------------
__global__ void __launch_bounds__(256, 2) k_scores() {
    int bx = blockIdx.x, by = blockIdx.y, hz = blockIdx.z;
    if (bx > by) return;
    extern __shared__ uint32_t smd[];
    WARP_IDS
    const bf16* Agh = qr_h + ((size_t)hz * T_ + by * 128) * NN_;
    const bf16* Agl = qr_l + ((size_t)hz * T_ + by * 128) * NN_;
    const bf16* Bgh = qr_h + ((size_t)hz * T_ + bx * 128) * NN_;
    const bf16* Bgl = qr_l + ((size_t)hz * T_ + bx * 128) * NN_;
    ZERO_ACC
    gemm_bf16(Agh, Agl, NN_, Bgh, Bgl, NN_, NN_, smd, acc, tid, wm, wn, grp, tig);

    const size_t hbase = (size_t)hz * T_ * T_;
    int t_blk = by * 128, u_blk = bx * 128;
    if (bx != by) {
        #pragma unroll
        for (int mi = 0; mi < 4; mi++)
            #pragma unroll
            for (int ni = 0; ni < 4; ni++) {
                int C0 = u_blk + wn + ni * 8 + 2 * tig;
                #pragma unroll
                for (int h2 = 0; h2 < 2; h2++) {
                    int t = t_blk + wm + mi * 16 + grp + 8 * h2;
                    st_split2(sc_h, sc_l, hbase + (size_t)t * T_ + C0,
                              acc[mi][ni][2 * h2], acc[mi][ni][2 * h2 + 1]);
                }
            }
    } else {
        #pragma unroll
        for (int mi = 0; mi < 4; mi++)
            #pragma unroll
            for (int ni = 0; ni < 4; ni++) {
                int C0 = u_blk + wn + ni * 8 + 2 * tig;
                #pragma unroll
                for (int h2 = 0; h2 < 2; h2++) {
                    int t = t_blk + wm + mi * 16 + grp + 8 * h2;
                    float v0 = (C0     < t) ? acc[mi][ni][2 * h2]     : 0.f;
                    float v1 = (C0 + 1 < t) ? acc[mi][ni][2 * h2 + 1] : 0.f;
                    st_split2(sc_h, sc_l, hbase + (size_t)t * T_ + C0, v0, v1);
                }
            }
    }
}

// ---------------- yKV_raw = scores @ x (K limited by causality) ----------------
__global__ void __launch_bounds__(256, 2) k_ykv() {
    extern __shared__ uint32_t smd[];
    WARP_IDS
    const int h = blockIdx.z;
    const int Kend = (blockIdx.y + 1) * 128;
    const bf16* Agh = sc_h + ((size_t)h * T_ + blockIdx.y * 128) * T_;
    const bf16* Agl = sc_l + ((size_t)h * T_ + blockIdx.y * 128) * T_;
    const bf16* Bgh = xT_h + (size_t)blockIdx.x * 128 * T_;
    const bf16* Bgl = xT_l + (size_t)blockIdx.x * 128 * T_;
    ZERO_ACC
    gemm_bf16(Agh, Agl, T_, Bgh, Bgl, T_, Kend, smd, acc, tid, wm, wn, grp, tig);
    store_plain(g_ykv + (size_t)h * T_ * D_, D_, blockIdx.y * 128, blockIdx.x * 128,
                acc, wm, wn, grp, tig);
}

// ---------------- LN(yKV) -> planes ----------------
__global__ void k_ln_ykv() {
    size_t r = blockIdx.x;
    int d = threadIdx.x;
    float v   = g_ykv[r * D_ + d];
    float m   = blk_sum256(v) * (1.0f / D_);
    float dv  = v - m;
    float var = blk_sum256(dv * dv) * (1.0f / D_);
    float y = dv * rsqrtf(var + EPS_);
    bf16 h = __float2bfloat16(y);
    yp_h[r * D_ + d] = h;
    yp_l[r * D_ + d] = __float2bfloat16(y - __bfloat162float(h));
}

// ---------------- decoder GEMM, split-K=8 ----------------
__global__ void __launch_bounds__(256, 2) k_dec() {
    extern __shared__ uint32_t smd[];
    WARP_IDS
    const int seg = blockIdx.z;
    const int h = seg >> 1;
    const int colb = (seg & 1) * 1024;
    const int t_blk = blockIdx.y * 128, c_blk = blockIdx.x * 128;
    const bf16* Agh = qr_h + ((size_t)h * T_ + t_blk) * NN_ + colb;
    const bf16* Agl = qr_l + ((size_t)h * T_ + t_blk) * NN_ + colb;
    const bf16* Bgh = decT_h + (size_t)c_blk * NHN_ + seg * 1024;
    const bf16* Bgl = decT_l + (size_t)c_blk * NHN_ + seg * 1024;
    ZERO_ACC
    gemm_bf16(Agh, Agl, NN_, Bgh, Bgl, NHN_, 1024, smd, acc, tid, wm, wn, grp, tig);
    store_plain(g_part + (size_t)seg * T_ * D_, D_, t_blk, c_blk, acc, wm, wn, grp, tig);
}

// ---------------- x = LN(x + LN(sum_partials)); refresh planes ----------------
__global__ void k_ln2() {
    int t = blockIdx.x, d = threadIdx.x;
    size_t o = (size_t)t * D_ + d;
    float y = 0.f;
    #pragma unroll
    for (int s = 0; s < 8; s++) y += g_part[(size_t)s * T_ * D_ + o];
    float m1 = blk_sum256(y) * (1.0f / D_);
    float dy = y - m1;
    float v1 = blk_sum256(dy * dy) * (1.0f / D_);
    float u  = dy * rsqrtf(v1 + EPS_);
    float w  = g_x[o] + u;
    float m2 = blk_sum256(w) * (1.0f / D_);
    float dw = w - m2;
    float v2 = blk_sum256(dw * dw) * (1.0f / D_);
    float x  = dw * rsqrtf(v2 + EPS_);
    g_x[o] = x;
    bf16 h = __float2bfloat16(x);
    bf16 l = __float2bfloat16(x - __bfloat162float(h));
    xp_h[o] = h; xp_l[o] = l;
    size_t ot = (size_t)d * T_ + t;
    xT_h[ot] = h; xT_l[ot] = l;
}

// ---------------- logits = x @ lm_head ----------------
__global__ void __launch_bounds__(256, 2) k_logits(float* __restrict__ out) {
    extern __shared__ uint32_t smd[];
    WARP_IDS
    const int t_blk = blockIdx.y * 128, c_blk = blockIdx.x * 128;
    const bf16* Agh = xp_h + (size_t)t_blk * D_;
    const bf16* Agl = xp_l + (size_t)t_blk * D_;
    const bf16* Bgh = lmhT_h + (size_t)c_blk * D_;
    const bf16* Bgl = lmhT_l + (size_t)c_blk * D_;
    ZERO_ACC
    gemm_bf16(Agh, Agl, D_, Bgh, Bgl, D_, D_, smd, acc, tid, wm, wn, grp, tig);
    store_plain(out, VOCAB_, t_blk, c_blk, acc, wm, wn, grp, tig);
}

// ---------------- host launch ----------------
extern "C" void kernel_launch(void* const* d_in, const int* in_sizes, int n_in,
                              void* d_out, int out_size) {
    (void)in_sizes; (void)n_in; (void)out_size;
    const int*   idx   = (const int*)d_in[0];
    const float* embed = (const float*)d_in[1];
    const float* enc   = (const float*)d_in[2];
    const float* encv  = (const float*)d_in[3];
    const float* dec   = (const float*)d_in[4];
    const float* lmh   = (const float*)d_in[5];
    float* out = (float*)d_out;

    cudaFuncSetAttribute(k_enc<1>, cudaFuncAttributeMaxDynamicSharedMemorySize, SMEM_DYN);
    cudaFuncSetAttribute(k_enc<4>, cudaFuncAttributeMaxDynamicSharedMemorySize, SMEM_DYN);
    cudaFuncSetAttribute(k_scores, cudaFuncAttributeMaxDynamicSharedMemorySize, SMEM_DYN);
    cudaFuncSetAttribute(k_ykv,    cudaFuncAttributeMaxDynamicSharedMemorySize, SMEM_DYN);
    cudaFuncSetAttribute(k_dec,    cudaFuncAttributeMaxDynamicSharedMemorySize, SMEM_DYN);
    cudaFuncSetAttribute(k_logits, cudaFuncAttributeMaxDynamicSharedMemorySize, SMEM_DYN);

    bf16 *p_encT_h, *p_encT_l, *p_envT_h, *p_envT_l, *p_decT_h, *p_decT_l, *p_lmhT_h, *p_lmhT_l;
    cudaGetSymbolAddress((void**)&p_encT_h, encT_h);
    cudaGetSymbolAddress((void**)&p_encT_l, encT_l);
    cudaGetSymbolAddress((void**)&p_envT_h, envT_h);
    cudaGetSymbolAddress((void**)&p_envT_l, envT_l);
    cudaGetSymbolAddress((void**)&p_decT_h, decT_h);
    cudaGetSymbolAddress((void**)&p_decT_l, decT_l);
    cudaGetSymbolAddress((void**)&p_lmhT_h, lmhT_h);
    cudaGetSymbolAddress((void**)&p_lmhT_l, lmhT_l);

    dim3 tb(32, 8);
    k_rope_tab<<<T_, 256>>>();
    k_tsplit<<<dim3(NN_ / 32, D_ / 32, NH_), tb>>>(enc,  p_encT_h, p_encT_l, D_, NN_);
    k_tsplit<<<dim3(NN_ / 32, D_ / 32, NH_), tb>>>(encv, p_envT_h, p_envT_l, D_, NN_);
    k_tsplit<<<dim3(D_ / 32, NHN_ / 32, 1), tb>>>(dec,  p_decT_h, p_decT_l, NHN_, D_);
    k_tsplit<<<dim3(VOCAB_ / 32, D_ / 32, 1), tb>>>(lmh, p_lmhT_h, p_lmhT_l, D_, VOCAB_);
    k_embed_ln<<<T_, 256>>>(idx, embed);

    for (int l = 0; l < NL_; ++l) {
        k_enc<1><<<dim3(16, 16, NH_), 256, SMEM_DYN>>>();
        k_scores<<<dim3(16, 16, NH_), 256, SMEM_DYN>>>();
        k_ykv<<<dim3(2, 16, NH_), 256, SMEM_DYN>>>();
        k_ln_ykv<<<NH_ * T_, 256>>>();
        k_enc<4><<<dim3(16, 16, NH_), 256, SMEM_DYN>>>();
        k_dec<<<dim3(2, 16, 8), 256, SMEM_DYN>>>();
        k_ln2<<<T_, 256>>>();
    }
    k_logits<<<dim3(2, 16, 1), 256, SMEM_DYN>>>(out);
}

// round 14
// speedup vs baseline: 1.3249x; 1.1987x over previous
#include <cuda_runtime.h>
#include <cuda_bf16.h>
#include <cstdint>
#include <cstddef>

#define T_    2048
#define D_    256
#define NN_   2048
#define NH_   4
#define NL_   6
#define VOCAB_ 256
#define NHN_  (NH_ * NN_)
#define EPS_  1e-5f
#define TWO_PI_ 6.283185307179586f
#define INV_2PI_ 0.15915494309189535f

typedef __nv_bfloat16 bf16;
typedef __nv_bfloat162 bf162;

// ---------------- scratch (device globals; no allocations) ----------------
__device__ float g_x   [(size_t)T_ * D_];
__device__ float g_pc  [(size_t)T_ * NN_];
__device__ float g_ps  [(size_t)T_ * NN_];
__device__ float g_xs  [(size_t)NH_ * T_ * NN_];
__device__ float g_ykv [(size_t)NH_ * T_ * D_];
__device__ float g_part[(size_t)8 * T_ * D_];

__device__ bf16 xp_h[(size_t)T_ * D_],    xp_l[(size_t)T_ * D_];
__device__ bf16 xT_h[(size_t)D_ * T_],    xT_l[(size_t)D_ * T_];
__device__ bf16 qr_h[(size_t)NH_ * T_ * NN_], qr_l[(size_t)NH_ * T_ * NN_];
__device__ bf16 sc_h[(size_t)NH_ * T_ * T_],  sc_l[(size_t)NH_ * T_ * T_];
__device__ bf16 yp_h[(size_t)NH_ * T_ * D_],  yp_l[(size_t)NH_ * T_ * D_];
__device__ bf16 encT_h[(size_t)NH_ * NN_ * D_], encT_l[(size_t)NH_ * NN_ * D_];
__device__ bf16 envT_h[(size_t)NH_ * NN_ * D_], envT_l[(size_t)NH_ * NN_ * D_];
__device__ bf16 decT_h[(size_t)D_ * NHN_],     decT_l[(size_t)D_ * NHN_];
__device__ bf16 lmhT_h[(size_t)VOCAB_ * D_],   lmhT_l[(size_t)VOCAB_ * D_];

// ---------------- small helpers ----------------
__device__ __forceinline__ uint32_t smem_u32(const void* p) {
    return (uint32_t)__cvta_generic_to_shared(p);
}
__device__ __forceinline__ void cpa16(uint32_t dst, const void* src) {
    asm volatile("cp.async.ca.shared.global [%0], [%1], 16;\n" :: "r"(dst), "l"(src));
}
__device__ __forceinline__ void cpa_commit() { asm volatile("cp.async.commit_group;\n"); }
template <int N>
__device__ __forceinline__ void cpa_wait() { asm volatile("cp.async.wait_group %0;\n" :: "n"(N)); }

__device__ __forceinline__ void mma16(float* c,
                                      uint32_t a0, uint32_t a1, uint32_t a2, uint32_t a3,
                                      uint32_t b0, uint32_t b1) {
    asm volatile(
        "mma.sync.aligned.m16n8k16.row.col.f32.bf16.bf16.f32 "
        "{%0,%1,%2,%3},{%4,%5,%6,%7},{%8,%9},{%0,%1,%2,%3};"
        : "+f"(c[0]), "+f"(c[1]), "+f"(c[2]), "+f"(c[3])
        : "r"(a0), "r"(a1), "r"(a2), "r"(a3), "r"(b0), "r"(b1));
}

__device__ __forceinline__ void ldsm4(uint32_t* r, uint32_t addr) {
    asm volatile("ldmatrix.sync.aligned.m8n8.x4.shared.b16 {%0,%1,%2,%3}, [%4];"
        : "=r"(r[0]), "=r"(r[1]), "=r"(r[2]), "=r"(r[3]) : "r"(addr));
}

// split fp32 -> bf16 hi + bf16 lo (pairwise store)
__device__ __forceinline__ void st_split2(bf16* H, bf16* L, size_t idx, float v0, float v1) {
    bf16 h0 = __float2bfloat16(v0), h1 = __float2bfloat16(v1);
    float r0 = v0 - __bfloat162float(h0), r1 = v1 - __bfloat162float(h1);
    bf162 hv; hv.x = h0; hv.y = h1;
    bf162 lv; lv.x = __float2bfloat16(r0); lv.y = __float2bfloat16(r1);
    *reinterpret_cast<bf162*>(H + idx) = hv;
    *reinterpret_cast<bf162*>(L + idx) = lv;
}

// ---------------- block reduction over 256 threads ----------------
__device__ __forceinline__ float blk_sum256(float v) {
    __shared__ float sb[8];
    #pragma unroll
    for (int o = 16; o; o >>= 1) v += __shfl_xor_sync(0xffffffffu, v, o);
    int tid = threadIdx.x;
    if ((tid & 31) == 0) sb[tid >> 5] = v;
    __syncthreads();
    if (tid == 0) {
        float s = 0.f;
        #pragma unroll
        for (int i = 0; i < 8; i++) s += sb[i];
        sb[0] = s;
    }
    __syncthreads();
    float r = sb[0];
    __syncthreads();
    return r;
}

// ---------------- core GEMM: 128x128 tile, K-tiles of 16, bf16 3-term ----------------
// plane layout: 128 rows x 48B stride, payload 32B = 16 bf16 (k16), ldmatrix-friendly.
// 8-row ldmatrix phase banks: 48B stride -> {0,12,24,4,16,28,8,20} conflict-free.
// 3-stage cp.async pipeline, one barrier per iteration (R13-proven ordering).
#define ROW_B     48
#define PLANE_B   (128 * ROW_B)      // 6144 bytes
#define STAGE_B   (4 * PLANE_B)      // Ah Al Bh Bl = 24576
#define STAGES    3
#define SMEM_DYN  (STAGES * STAGE_B) // 73728 bytes

__device__ __forceinline__ void gemm_bf16(
    const bf16* __restrict__ Agh, const bf16* __restrict__ Agl, int lda,
    const bf16* __restrict__ Bgh, const bf16* __restrict__ Bgl, int ldb,
    int K, uint32_t sbase, float (&acc)[4][4][4],
    int tid, int lane, int wm, int wn)
{
    const int NT   = K >> 4;
    const int row  = tid >> 1;
    const int half = tid & 1;
    const uint32_t doff = (uint32_t)(row * ROW_B + half * 16);
    const int go = half * 8;

    // ldmatrix per-lane offsets (bytes within a plane)
    uint32_t aoff[4], boff[2];
    {
        int r8 = ((lane >> 3) & 1) * 8 + (lane & 7);
        int kb16 = (lane >> 4) * 16;
        #pragma unroll
        for (int mi = 0; mi < 4; mi++)
            aoff[mi] = (uint32_t)((wm + mi * 16 + r8) * ROW_B + kb16);
        int rB = ((lane >> 4) & 1) * 8 + (lane & 7);
        int kbB = ((lane >> 3) & 1) * 16;
        #pragma unroll
        for (int n2 = 0; n2 < 2; n2++)
            boff[n2] = (uint32_t)((wn + n2 * 16 + rB) * ROW_B + kbB);
    }

    auto issue = [&](int it) {
        int kb = it << 4;
        uint32_t st = sbase + (uint32_t)(it % STAGES) * STAGE_B;
        cpa16(st + doff,               Agh + (size_t)row * lda + kb + go);
        cpa16(st + PLANE_B + doff,     Agl + (size_t)row * lda + kb + go);
        cpa16(st + 2 * PLANE_B + doff, Bgh + (size_t)row * ldb + kb + go);
        cpa16(st + 3 * PLANE_B + doff, Bgl + (size_t)row * ldb + kb + go);
        cpa_commit();
    };

    issue(0);
    issue(1);

    for (int it = 0; it < NT; ++it) {
        if (it + 1 < NT) cpa_wait<1>();
        else             cpa_wait<0>();
        __syncthreads();   // all threads' group(it) complete; all compute(it-1) done

        uint32_t st = sbase + (uint32_t)(it % STAGES) * STAGE_B;

        uint32_t ah[4][4], al[4][4];
        #pragma unroll
        for (int mi = 0; mi < 4; mi++) ldsm4(ah[mi], st + aoff[mi]);
        #pragma unroll
        for (int mi = 0; mi < 4; mi++) ldsm4(al[mi], st + PLANE_B + aoff[mi]);

        #pragma unroll
        for (int n2 = 0; n2 < 2; n2++) {
            uint32_t bh[4], bl[4];
            ldsm4(bh, st + 2 * PLANE_B + boff[n2]);
            ldsm4(bl, st + 3 * PLANE_B + boff[n2]);
            #pragma unroll
            for (int hf = 0; hf < 2; hf++) {
                int ni = n2 * 2 + hf;
                uint32_t b0h = bh[hf * 2], b1h = bh[hf * 2 + 1];
                uint32_t b0l = bl[hf * 2], b1l = bl[hf * 2 + 1];
                #pragma unroll
                for (int mi = 0; mi < 4; mi++) {
                    mma16(acc[mi][ni], ah[mi][0], ah[mi][1], ah[mi][2], ah[mi][3], b0h, b1h);
                    mma16(acc[mi][ni], al[mi][0], al[mi][1], al[mi][2], al[mi][3], b0h, b1h);
                    mma16(acc[mi][ni], ah[mi][0], ah[mi][1], ah[mi][2], ah[mi][3], b0l, b1l);
                }
            }
        }

        if (it + 2 < NT) issue(it + 2);
    }
    __syncthreads();
}

#define WARP_IDS                                   \
    const int tid = threadIdx.x;                   \
    const int lane = tid & 31, warp = tid >> 5;    \
    const int grp = lane >> 2, tig = lane & 3;     \
    const int wm = (warp >> 2) * 64, wn = (warp & 3) * 32;

#define ZERO_ACC float acc[4][4][4];               \
    _Pragma("unroll") for (int i = 0; i < 4; i++)  \
    _Pragma("unroll") for (int j = 0; j < 4; j++)  \
    _Pragma("unroll") for (int r = 0; r < 4; r++) acc[i][j][r] = 0.f;

// plain fp32 store of the 128x128 tile
__device__ __forceinline__ void store_plain(float* __restrict__ Cb, int ldc,
                                            int t_blk, int c_blk, const float (&acc)[4][4][4],
                                            int wm, int wn, int grp, int tig) {
    #pragma unroll
    for (int mi = 0; mi < 4; mi++)
        #pragma unroll
        for (int ni = 0; ni < 4; ni++) {
            int col = c_blk + wn + ni * 8 + 2 * tig;
            #pragma unroll
            for (int h = 0; h < 2; h++) {
                int row = t_blk + wm + mi * 16 + grp + 8 * h;
                float2 v = make_float2(acc[mi][ni][2 * h], acc[mi][ni][2 * h + 1]);
                *reinterpret_cast<float2*>(&Cb[(size_t)row * ldc + col]) = v;
            }
        }
}

// ---------------- prep: transpose fp32 [R][C] -> bf16 hi/lo planes [C][R] ----------------
__global__ void k_tsplit(const float* __restrict__ src, bf16* __restrict__ H,
                         bf16* __restrict__ L, int R, int C) {
    __shared__ float s[32][33];
    size_t zo  = (size_t)blockIdx.z * R * C;
    int c0 = blockIdx.x * 32, r0 = blockIdx.y * 32;
    #pragma unroll
    for (int i = 0; i < 4; i++) {
        int r = r0 + threadIdx.y + i * 8;
        s[threadIdx.y + i * 8][threadIdx.x] = src[zo + (size_t)r * C + c0 + threadIdx.x];
    }
    __syncthreads();
    size_t zo2 = (size_t)blockIdx.z * C * R;
    #pragma unroll
    for (int i = 0; i < 4; i++) {
        int c = c0 + threadIdx.y + i * 8;
        float v = s[threadIdx.x][threadIdx.y + i * 8];
        bf16 h = __float2bfloat16(v);
        size_t o = zo2 + (size_t)c * R + r0 + threadIdx.x;
        H[o] = h;
        L[o] = __float2bfloat16(v - __bfloat162float(h));
    }
}

// ---------------- RoPE cos/sin tables ----------------
__global__ void k_rope_tab() {
    int t = blockIdx.x;
    for (int n = threadIdx.x; n < NN_; n += 256) {
        float q    = (float)(n & ~1);
        float freq = exp2f(-q * (1.0f / 128.0f)) * INV_2PI_;   // THETA = 2^16
        float ph   = fmodf((float)t * freq, 1.0f) * TWO_PI_;
        float s, c;
        sincosf(ph, &s, &c);
        g_pc[(size_t)t * NN_ + n] = c;
        g_ps[(size_t)t * NN_ + n] = s;
    }
}

// ---------------- x = LN(embed[idx]); write fp32 + planes + transposed planes ----------------
__global__ void k_embed_ln(const int* __restrict__ idx, const float* __restrict__ embed) {
    int t = blockIdx.x, d = threadIdx.x;
    float v   = embed[(size_t)idx[t] * D_ + d];
    float m   = blk_sum256(v) * (1.0f / D_);
    float dv  = v - m;
    float var = blk_sum256(dv * dv) * (1.0f / D_);
    float x = dv * rsqrtf(var + EPS_);
    size_t o = (size_t)t * D_ + d;
    g_x[o] = x;
    bf16 h = __float2bfloat16(x);
    bf16 l = __float2bfloat16(x - __bfloat162float(h));
    xp_h[o] = h; xp_l[o] = l;
    size_t ot = (size_t)d * T_ + t;
    xT_h[ot] = h; xT_l[ot] = l;
}

// ---------------- enc GEMM: MODE 1: xs=relu(x@enc), qr=rope(xs)
// ----------------           MODE 4: xy = relu(yKV@encv) * xs (into qr planes)
template <int MODE>
__global__ void __launch_bounds__(256, 2) k_enc() {
    extern __shared__ uint32_t smd[];
    WARP_IDS
    const int h = blockIdx.z;
    const int t_blk = blockIdx.y * 128, n_blk = blockIdx.x * 128;
    const bf16 *Agh, *Agl, *Bgh, *Bgl;
    if (MODE == 1) {
        Agh = xp_h + (size_t)t_blk * D_;
        Agl = xp_l + (size_t)t_blk * D_;
        Bgh = encT_h + ((size_t)h * NN_ + n_blk) * D_;
        Bgl = encT_l + ((size_t)h * NN_ + n_blk) * D_;
    } else {
        Agh = yp_h + ((size_t)h * T_ + t_blk) * D_;
        Agl = yp_l + ((size_t)h * T_ + t_blk) * D_;
        Bgh = envT_h + ((size_t)h * NN_ + n_blk) * D_;
        Bgl = envT_l + ((size_t)h * NN_ + n_blk) * D_;
    }
    ZERO_ACC
    gemm_bf16(Agh, Agl, D_, Bgh, Bgl, D_, D_, smem_u32(smd), acc, tid, lane, wm, wn);

    const size_t hbase = (size_t)h * T_ * NN_;
    #pragma unroll
    for (int mi = 0; mi < 4; mi++)
        #pragma unroll
        for (int ni = 0; ni < 4; ni++) {
            int C0 = n_blk + wn + ni * 8 + 2 * tig;
            #pragma unroll
            for (int hh = 0; hh < 2; hh++) {
                int t = t_blk + wm + mi * 16 + grp + 8 * hh;
                float v0 = fmaxf(acc[mi][ni][2 * hh], 0.f);
                float v1 = fmaxf(acc[mi][ni][2 * hh + 1], 0.f);
                size_t rb = hbase + (size_t)t * NN_ + C0;
                if (MODE == 1) {
                    *reinterpret_cast<float2*>(&g_xs[rb]) = make_float2(v0, v1);
                    float2 pc = *reinterpret_cast<const float2*>(&g_pc[(size_t)t * NN_ + C0]);
                    float2 ps = *reinterpret_cast<const float2*>(&g_ps[(size_t)t * NN_ + C0]);
                    float q0 = v0 * pc.x - v1 * ps.x;
                    float q1 = v1 * pc.y + v0 * ps.y;
                    st_split2(qr_h, qr_l, rb, q0, q1);
                } else {
                    float2 xs = *reinterpret_cast<const float2*>(&g_xs[rb]);
                    st_split2(qr_h, qr_l, rb, v0 * xs.x, v1 * xs.y);
                }
            }
        }
}

// ---------------- scores = tril(qr @ qr^T, k=-1) into sc planes ----------------
__global__ void __launch_bounds__(256, 2) k_scores() {
    int bx = blockIdx.x, by = blockIdx.y, hz = blockIdx.z;
    if (bx > by) return;
    extern __shared__ uint32_t smd[];
    WARP_IDS
    const bf16* Agh = qr_h + ((size_t)hz * T_ + by * 128) * NN_;
    const bf16* Agl = qr_l + ((size_t)hz * T_ + by * 128) * NN_;
    const bf16* Bgh = qr_h + ((size_t)hz * T_ + bx * 128) * NN_;
    const bf16* Bgl = qr_l + ((size_t)hz * T_ + bx * 128) * NN_;
    ZERO_ACC
    gemm_bf16(Agh, Agl, NN_, Bgh, Bgl, NN_, NN_, smem_u32(smd), acc, tid, lane, wm, wn);

    const size_t hbase = (size_t)hz * T_ * T_;
    int t_blk = by * 128, u_blk = bx * 128;
    if (bx != by) {
        #pragma unroll
        for (int mi = 0; mi < 4; mi++)
            #pragma unroll
            for (int ni = 0; ni < 4; ni++) {
                int C0 = u_blk + wn + ni * 8 + 2 * tig;
                #pragma unroll
                for (int h2 = 0; h2 < 2; h2++) {
                    int t = t_blk + wm + mi * 16 + grp + 8 * h2;
                    st_split2(sc_h, sc_l, hbase + (size_t)t * T_ + C0,
                              acc[mi][ni][2 * h2], acc[mi][ni][2 * h2 + 1]);
                }
            }
    } else {
        #pragma unroll
        for (int mi = 0; mi < 4; mi++)
            #pragma unroll
            for (int ni = 0; ni < 4; ni++) {
                int C0 = u_blk + wn + ni * 8 + 2 * tig;
                #pragma unroll
                for (int h2 = 0; h2 < 2; h2++) {
                    int t = t_blk + wm + mi * 16 + grp + 8 * h2;
                    float v0 = (C0     < t) ? acc[mi][ni][2 * h2]     : 0.f;
                    float v1 = (C0 + 1 < t) ? acc[mi][ni][2 * h2 + 1] : 0.f;
                    st_split2(sc_h, sc_l, hbase + (size_t)t * T_ + C0, v0, v1);
                }
            }
    }
}

// ---------------- yKV_raw = scores @ x (K limited by causality) ----------------
__global__ void __launch_bounds__(256, 2) k_ykv() {
    extern __shared__ uint32_t smd[];
    WARP_IDS
    const int h = blockIdx.z;
    const int Kend = (blockIdx.y + 1) * 128;
    const bf16* Agh = sc_h + ((size_t)h * T_ + blockIdx.y * 128) * T_;
    const bf16* Agl = sc_l + ((size_t)h * T_ + blockIdx.y * 128) * T_;
    const bf16* Bgh = xT_h + (size_t)blockIdx.x * 128 * T_;
    const bf16* Bgl = xT_l + (size_t)blockIdx.x * 128 * T_;
    ZERO_ACC
    gemm_bf16(Agh, Agl, T_, Bgh, Bgl, T_, Kend, smem_u32(smd), acc, tid, lane, wm, wn);
    store_plain(g_ykv + (size_t)h * T_ * D_, D_, blockIdx.y * 128, blockIdx.x * 128,
                acc, wm, wn, grp, tig);
}

// ---------------- LN(yKV) -> planes ----------------
__global__ void k_ln_ykv() {
    size_t r = blockIdx.x;
    int d = threadIdx.x;
    float v   = g_ykv[r * D_ + d];
    float m   = blk_sum256(v) * (1.0f / D_);
    float dv  = v - m;
    float var = blk_sum256(dv * dv) * (1.0f / D_);
    float y = dv * rsqrtf(var + EPS_);
    bf16 h = __float2bfloat16(y);
    yp_h[r * D_ + d] = h;
    yp_l[r * D_ + d] = __float2bfloat16(y - __bfloat162float(h));
}

// ---------------- decoder GEMM, split-K=8 ----------------
__global__ void __launch_bounds__(256, 2) k_dec() {
    extern __shared__ uint32_t smd[];
    WARP_IDS
    const int seg = blockIdx.z;
    const int h = seg >> 1;
    const int colb = (seg & 1) * 1024;
    const int t_blk = blockIdx.y * 128, c_blk = blockIdx.x * 128;
    const bf16* Agh = qr_h + ((size_t)h * T_ + t_blk) * NN_ + colb;
    const bf16* Agl = qr_l + ((size_t)h * T_ + t_blk) * NN_ + colb;
    const bf16* Bgh = decT_h + (size_t)c_blk * NHN_ + seg * 1024;
    const bf16* Bgl = decT_l + (size_t)c_blk * NHN_ + seg * 1024;
    ZERO_ACC
    gemm_bf16(Agh, Agl, NN_, Bgh, Bgl, NHN_, 1024, smem_u32(smd), acc, tid, lane, wm, wn);
    store_plain(g_part + (size_t)seg * T_ * D_, D_, t_blk, c_blk, acc, wm, wn, grp, tig);
}

// ---------------- x = LN(x + LN(sum_partials)); refresh planes ----------------
__global__ void k_ln2() {
    int t = blockIdx.x, d = threadIdx.x;
    size_t o = (size_t)t * D_ + d;
    float y = 0.f;
    #pragma unroll
    for (int s = 0; s < 8; s++) y += g_part[(size_t)s * T_ * D_ + o];
    float m1 = blk_sum256(y) * (1.0f / D_);
    float dy = y - m1;
    float v1 = blk_sum256(dy * dy) * (1.0f / D_);
    float u  = dy * rsqrtf(v1 + EPS_);
    float w  = g_x[o] + u;
    float m2 = blk_sum256(w) * (1.0f / D_);
    float dw = w - m2;
    float v2 = blk_sum256(dw * dw) * (1.0f / D_);
    float x  = dw * rsqrtf(v2 + EPS_);
    g_x[o] = x;
    bf16 h = __float2bfloat16(x);
    bf16 l = __float2bfloat16(x - __bfloat162float(h));
    xp_h[o] = h; xp_l[o] = l;
    size_t ot = (size_t)d * T_ + t;
    xT_h[ot] = h; xT_l[ot] = l;
}

// ---------------- logits = x @ lm_head ----------------
__global__ void __launch_bounds__(256, 2) k_logits(float* __restrict__ out) {
    extern __shared__ uint32_t smd[];
    WARP_IDS
    const int t_blk = blockIdx.y * 128, c_blk = blockIdx.x * 128;
    const bf16* Agh = xp_h + (size_t)t_blk * D_;
    const bf16* Agl = xp_l + (size_t)t_blk * D_;
    const bf16* Bgh = lmhT_h + (size_t)c_blk * D_;
    const bf16* Bgl = lmhT_l + (size_t)c_blk * D_;
    ZERO_ACC
    gemm_bf16(Agh, Agl, D_, Bgh, Bgl, D_, D_, smem_u32(smd), acc, tid, lane, wm, wn);
    store_plain(out, VOCAB_, t_blk, c_blk, acc, wm, wn, grp, tig);
}

// ---------------- host launch ----------------
extern "C" void kernel_launch(void* const* d_in, const int* in_sizes, int n_in,
                              void* d_out, int out_size) {
    (void)in_sizes; (void)n_in; (void)out_size;
    const int*   idx   = (const int*)d_in[0];
    const float* embed = (const float*)d_in[1];
    const float* enc   = (const float*)d_in[2];
    const float* encv  = (const float*)d_in[3];
    const float* dec   = (const float*)d_in[4];
    const float* lmh   = (const float*)d_in[5];
    float* out = (float*)d_out;

    cudaFuncSetAttribute(k_enc<1>, cudaFuncAttributeMaxDynamicSharedMemorySize, SMEM_DYN);
    cudaFuncSetAttribute(k_enc<4>, cudaFuncAttributeMaxDynamicSharedMemorySize, SMEM_DYN);
    cudaFuncSetAttribute(k_scores, cudaFuncAttributeMaxDynamicSharedMemorySize, SMEM_DYN);
    cudaFuncSetAttribute(k_ykv,    cudaFuncAttributeMaxDynamicSharedMemorySize, SMEM_DYN);
    cudaFuncSetAttribute(k_dec,    cudaFuncAttributeMaxDynamicSharedMemorySize, SMEM_DYN);
    cudaFuncSetAttribute(k_logits, cudaFuncAttributeMaxDynamicSharedMemorySize, SMEM_DYN);

    bf16 *p_encT_h, *p_encT_l, *p_envT_h, *p_envT_l, *p_decT_h, *p_decT_l, *p_lmhT_h, *p_lmhT_l;
    cudaGetSymbolAddress((void**)&p_encT_h, encT_h);
    cudaGetSymbolAddress((void**)&p_encT_l, encT_l);
    cudaGetSymbolAddress((void**)&p_envT_h, envT_h);
    cudaGetSymbolAddress((void**)&p_envT_l, envT_l);
    cudaGetSymbolAddress((void**)&p_decT_h, decT_h);
    cudaGetSymbolAddress((void**)&p_decT_l, decT_l);
    cudaGetSymbolAddress((void**)&p_lmhT_h, lmhT_h);
    cudaGetSymbolAddress((void**)&p_lmhT_l, lmhT_l);

    dim3 tb(32, 8);
    k_rope_tab<<<T_, 256>>>();
    k_tsplit<<<dim3(NN_ / 32, D_ / 32, NH_), tb>>>(enc,  p_encT_h, p_encT_l, D_, NN_);
    k_tsplit<<<dim3(NN_ / 32, D_ / 32, NH_), tb>>>(encv, p_envT_h, p_envT_l, D_, NN_);
    k_tsplit<<<dim3(D_ / 32, NHN_ / 32, 1), tb>>>(dec,  p_decT_h, p_decT_l, NHN_, D_);
    k_tsplit<<<dim3(VOCAB_ / 32, D_ / 32, 1), tb>>>(lmh, p_lmhT_h, p_lmhT_l, D_, VOCAB_);
    k_embed_ln<<<T_, 256>>>(idx, embed);

    for (int l = 0; l < NL_; ++l) {
        k_enc<1><<<dim3(16, 16, NH_), 256, SMEM_DYN>>>();
        k_scores<<<dim3(16, 16, NH_), 256, SMEM_DYN>>>();
        k_ykv<<<dim3(2, 16, NH_), 256, SMEM_DYN>>>();
        k_ln_ykv<<<NH_ * T_, 256>>>();
        k_enc<4><<<dim3(16, 16, NH_), 256, SMEM_DYN>>>();
        k_dec<<<dim3(2, 16, 8), 256, SMEM_DYN>>>();
        k_ln2<<<T_, 256>>>();
    }
    k_logits<<<dim3(2, 16, 1), 256, SMEM_DYN>>>(out);
}

// round 16
// speedup vs baseline: 1.3312x; 1.0047x over previous
#include <cuda_runtime.h>
#include <cuda_bf16.h>
#include <cstdint>
#include <cstddef>

#define T_    2048
#define D_    256
#define NN_   2048
#define NH_   4
#define NL_   6
#define VOCAB_ 256
#define NHN_  (NH_ * NN_)
#define EPS_  1e-5f
#define TWO_PI_ 6.283185307179586f
#define INV_2PI_ 0.15915494309189535f

typedef __nv_bfloat16 bf16;
typedef __nv_bfloat162 bf162;

// ---------------- scratch (device globals; no allocations) ----------------
__device__ float g_x   [(size_t)T_ * D_];
__device__ float g_pc  [(size_t)T_ * (NN_ / 2)];   // pair-deduped rope cos
__device__ float g_ps  [(size_t)T_ * (NN_ / 2)];   // pair-deduped rope sin
__device__ float g_xs  [(size_t)NH_ * T_ * NN_];
__device__ float g_part[(size_t)8 * T_ * D_];      // ykv split-K partials / dec split-K partials

__device__ bf16 xp_h[(size_t)T_ * D_],    xp_l[(size_t)T_ * D_];
__device__ bf16 xT_h[(size_t)D_ * T_],    xT_l[(size_t)D_ * T_];
__device__ bf16 qr_h[(size_t)NH_ * T_ * NN_], qr_l[(size_t)NH_ * T_ * NN_];
__device__ bf16 sc_h[(size_t)NH_ * T_ * T_],  sc_l[(size_t)NH_ * T_ * T_];
__device__ bf16 yp_h[(size_t)NH_ * T_ * D_],  yp_l[(size_t)NH_ * T_ * D_];
__device__ bf16 encT_h[(size_t)NH_ * NN_ * D_], encT_l[(size_t)NH_ * NN_ * D_];
__device__ bf16 envT_h[(size_t)NH_ * NN_ * D_], envT_l[(size_t)NH_ * NN_ * D_];
__device__ bf16 decT_h[(size_t)D_ * NHN_],     decT_l[(size_t)D_ * NHN_];
__device__ bf16 lmhT_h[(size_t)VOCAB_ * D_],   lmhT_l[(size_t)VOCAB_ * D_];

// ---------------- small helpers ----------------
__device__ __forceinline__ uint32_t smem_u32(const void* p) {
    return (uint32_t)__cvta_generic_to_shared(p);
}
__device__ __forceinline__ void cpa16(uint32_t dst, const void* src) {
    asm volatile("cp.async.ca.shared.global [%0], [%1], 16;\n" :: "r"(dst), "l"(src));
}
__device__ __forceinline__ void cpa_commit() { asm volatile("cp.async.commit_group;\n"); }
template <int N>
__device__ __forceinline__ void cpa_wait() { asm volatile("cp.async.wait_group %0;\n" :: "n"(N)); }

__device__ __forceinline__ void mma16(float* c,
                                      uint32_t a0, uint32_t a1, uint32_t a2, uint32_t a3,
                                      uint32_t b0, uint32_t b1) {
    asm volatile(
        "mma.sync.aligned.m16n8k16.row.col.f32.bf16.bf16.f32 "
        "{%0,%1,%2,%3},{%4,%5,%6,%7},{%8,%9},{%0,%1,%2,%3};"
        : "+f"(c[0]), "+f"(c[1]), "+f"(c[2]), "+f"(c[3])
        : "r"(a0), "r"(a1), "r"(a2), "r"(a3), "r"(b0), "r"(b1));
}

__device__ __forceinline__ void ldsm4(uint32_t* r, uint32_t addr) {
    asm volatile("ldmatrix.sync.aligned.m8n8.x4.shared.b16 {%0,%1,%2,%3}, [%4];"
        : "=r"(r[0]), "=r"(r[1]), "=r"(r[2]), "=r"(r[3]) : "r"(addr));
}

// split fp32 -> bf16 hi + bf16 lo (pairwise store)
__device__ __forceinline__ void st_split2(bf16* H, bf16* L, size_t idx, float v0, float v1) {
    bf16 h0 = __float2bfloat16(v0), h1 = __float2bfloat16(v1);
    float r0 = v0 - __bfloat162float(h0), r1 = v1 - __bfloat162float(h1);
    bf162 hv; hv.x = h0; hv.y = h1;
    bf162 lv; lv.x = __float2bfloat16(r0); lv.y = __float2bfloat16(r1);
    *reinterpret_cast<bf162*>(H + idx) = hv;
    *reinterpret_cast<bf162*>(L + idx) = lv;
}

// ---------------- block reduction over 256 threads ----------------
__device__ __forceinline__ float blk_sum256(float v) {
    __shared__ float sb[8];
    #pragma unroll
    for (int o = 16; o; o >>= 1) v += __shfl_xor_sync(0xffffffffu, v, o);
    int tid = threadIdx.x;
    if ((tid & 31) == 0) sb[tid >> 5] = v;
    __syncthreads();
    if (tid == 0) {
        float s = 0.f;
        #pragma unroll
        for (int i = 0; i < 8; i++) s += sb[i];
        sb[0] = s;
    }
    __syncthreads();
    float r = sb[0];
    __syncthreads();
    return r;
}

// ---------------- core GEMM: 128x128 tile, K-tiles of 16, bf16 3-term ----------------
// plane layout: 128 rows x 48B stride, payload 32B = 16 bf16 (k16), ldmatrix-friendly.
// 3-stage cp.async pipeline, one barrier per iteration (R13/R14-proven ordering).
#define ROW_B     48
#define PLANE_B   (128 * ROW_B)      // 6144 bytes
#define STAGE_B   (4 * PLANE_B)      // Ah Al Bh Bl = 24576
#define STAGES    3
#define SMEM_DYN  (STAGES * STAGE_B) // 73728 bytes

__device__ __forceinline__ void gemm_bf16(
    const bf16* __restrict__ Agh, const bf16* __restrict__ Agl, int lda,
    const bf16* __restrict__ Bgh, const bf16* __restrict__ Bgl, int ldb,
    int K, uint32_t sbase, float (&acc)[4][4][4],
    int tid, int lane, int wm, int wn)
{
    const int NT   = K >> 4;
    const int row  = tid >> 1;
    const int half = tid & 1;
    const uint32_t doff = (uint32_t)(row * ROW_B + half * 16);
    const int go = half * 8;

    uint32_t aoff[4], boff[2];
    {
        int r8 = ((lane >> 3) & 1) * 8 + (lane & 7);
        int kb16 = (lane >> 4) * 16;
        #pragma unroll
        for (int mi = 0; mi < 4; mi++)
            aoff[mi] = (uint32_t)((wm + mi * 16 + r8) * ROW_B + kb16);
        int rB = ((lane >> 4) & 1) * 8 + (lane & 7);
        int kbB = ((lane >> 3) & 1) * 16;
        #pragma unroll
        for (int n2 = 0; n2 < 2; n2++)
            boff[n2] = (uint32_t)((wn + n2 * 16 + rB) * ROW_B + kbB);
    }

    auto issue = [&](int it) {
        int kb = it << 4;
        uint32_t st = sbase + (uint32_t)(it % STAGES) * STAGE_B;
        cpa16(st + doff,               Agh + (size_t)row * lda + kb + go);
        cpa16(st + PLANE_B + doff,     Agl + (size_t)row * lda + kb + go);
        cpa16(st + 2 * PLANE_B + doff, Bgh + (size_t)row * ldb + kb + go);
        cpa16(st + 3 * PLANE_B + doff, Bgl + (size_t)row * ldb + kb + go);
        cpa_commit();
    };

    issue(0);
    issue(1);

    for (int it = 0; it < NT; ++it) {
        if (it + 1 < NT) cpa_wait<1>();
        else             cpa_wait<0>();
        __syncthreads();

        uint32_t st = sbase + (uint32_t)(it % STAGES) * STAGE_B;

        uint32_t ah[4][4], al[4][4];
        #pragma unroll
        for (int mi = 0; mi < 4; mi++) ldsm4(ah[mi], st + aoff[mi]);
        #pragma unroll
        for (int mi = 0; mi < 4; mi++) ldsm4(al[mi], st + PLANE_B + aoff[mi]);

        #pragma unroll
        for (int n2 = 0; n2 < 2; n2++) {
            uint32_t bh[4], bl[4];
            ldsm4(bh, st + 2 * PLANE_B + boff[n2]);
            ldsm4(bl, st + 3 * PLANE_B + boff[n2]);
            #pragma unroll
            for (int hf = 0; hf < 2; hf++) {
                int ni = n2 * 2 + hf;
                uint32_t b0h = bh[hf * 2], b1h = bh[hf * 2 + 1];
                uint32_t b0l = bl[hf * 2], b1l = bl[hf * 2 + 1];
                #pragma unroll
                for (int mi = 0; mi < 4; mi++) {
                    mma16(acc[mi][ni], ah[mi][0], ah[mi][1], ah[mi][2], ah[mi][3], b0h, b1h);
                    mma16(acc[mi][ni], al[mi][0], al[mi][1], al[mi][2], al[mi][3], b0h, b1h);
                    mma16(acc[mi][ni], ah[mi][0], ah[mi][1], ah[mi][2], ah[mi][3], b0l, b1l);
                }
            }
        }

        if (it + 2 < NT) issue(it + 2);
    }
    __syncthreads();
}

#define WARP_IDS                                   \
    const int tid = threadIdx.x;                   \
    const int lane = tid & 31, warp = tid >> 5;    \
    const int grp = lane >> 2, tig = lane & 3;     \
    const int wm = (warp >> 2) * 64, wn = (warp & 3) * 32;

#define ZERO_ACC float acc[4][4][4];               \
    _Pragma("unroll") for (int i = 0; i < 4; i++)  \
    _Pragma("unroll") for (int j = 0; j < 4; j++)  \
    _Pragma("unroll") for (int r = 0; r < 4; r++) acc[i][j][r] = 0.f;

// plain fp32 store of the 128x128 tile
__device__ __forceinline__ void store_plain(float* __restrict__ Cb, int ldc,
                                            int t_blk, int c_blk, const float (&acc)[4][4][4],
                                            int wm, int wn, int grp, int tig) {
    #pragma unroll
    for (int mi = 0; mi < 4; mi++)
        #pragma unroll
        for (int ni = 0; ni < 4; ni++) {
            int col = c_blk + wn + ni * 8 + 2 * tig;
            #pragma unroll
            for (int h = 0; h < 2; h++) {
                int row = t_blk + wm + mi * 16 + grp + 8 * h;
                float2 v = make_float2(acc[mi][ni][2 * h], acc[mi][ni][2 * h + 1]);
                *reinterpret_cast<float2*>(&Cb[(size_t)row * ldc + col]) = v;
            }
        }
}

// ---------------- prep: transpose fp32 [R][C] -> bf16 hi/lo planes [C][R] ----------------
__global__ void k_tsplit(const float* __restrict__ src, bf16* __restrict__ H,
                         bf16* __restrict__ L, int R, int C) {
    __shared__ float s[32][33];
    size_t zo  = (size_t)blockIdx.z * R * C;
    int c0 = blockIdx.x * 32, r0 = blockIdx.y * 32;
    #pragma unroll
    for (int i = 0; i < 4; i++) {
        int r = r0 + threadIdx.y + i * 8;
        s[threadIdx.y + i * 8][threadIdx.x] = src[zo + (size_t)r * C + c0 + threadIdx.x];
    }
    __syncthreads();
    size_t zo2 = (size_t)blockIdx.z * C * R;
    #pragma unroll
    for (int i = 0; i < 4; i++) {
        int c = c0 + threadIdx.y + i * 8;
        float v = s[threadIdx.x][threadIdx.y + i * 8];
        bf16 h = __float2bfloat16(v);
        size_t o = zo2 + (size_t)c * R + r0 + threadIdx.x;
        H[o] = h;
        L[o] = __float2bfloat16(v - __bfloat162float(h));
    }
}

// ---------------- RoPE cos/sin tables (pair-deduped: one entry per even n) ------------
__global__ void k_rope_tab() {
    int t = blockIdx.x;
    for (int p = threadIdx.x; p < NN_ / 2; p += 256) {
        float q    = (float)(2 * p);
        float freq = exp2f(-q * (1.0f / 128.0f)) * INV_2PI_;   // THETA = 2^16
        float ph   = fmodf((float)t * freq, 1.0f) * TWO_PI_;
        float s, c;
        sincosf(ph, &s, &c);
        g_pc[(size_t)t * (NN_ / 2) + p] = c;
        g_ps[(size_t)t * (NN_ / 2) + p] = s;
    }
}

// ---------------- x = LN(embed[idx]); write fp32 + planes + transposed planes ---------
__global__ void k_embed_ln(const int* __restrict__ idx, const float* __restrict__ embed) {
    int t = blockIdx.x, d = threadIdx.x;
    float v   = embed[(size_t)idx[t] * D_ + d];
    float m   = blk_sum256(v) * (1.0f / D_);
    float dv  = v - m;
    float var = blk_sum256(dv * dv) * (1.0f / D_);
    float x = dv * rsqrtf(var + EPS_);
    size_t o = (size_t)t * D_ + d;
    g_x[o] = x;
    bf16 h = __float2bfloat16(x);
    bf16 l = __float2bfloat16(x - __bfloat162float(h));
    xp_h[o] = h; xp_l[o] = l;
    size_t ot = (size_t)d * T_ + t;
    xT_h[ot] = h; xT_l[ot] = l;
}

// ---------------- enc GEMM: MODE 1: xs=relu(x@enc), qr=rope(xs)
// ----------------           MODE 4: xy = relu(yKV@encv) * xs (into qr planes)
template <int MODE>
__global__ void __launch_bounds__(256, 2) k_enc() {
    extern __shared__ uint32_t smd[];
    WARP_IDS
    const int h = blockIdx.z;
    const int t_blk = blockIdx.y * 128, n_blk = blockIdx.x * 128;
    const bf16 *Agh, *Agl, *Bgh, *Bgl;
    if (MODE == 1) {
        Agh = xp_h + (size_t)t_blk * D_;
        Agl = xp_l + (size_t)t_blk * D_;
        Bgh = encT_h + ((size_t)h * NN_ + n_blk) * D_;
        Bgl = encT_l + ((size_t)h * NN_ + n_blk) * D_;
    } else {
        Agh = yp_h + ((size_t)h * T_ + t_blk) * D_;
        Agl = yp_l + ((size_t)h * T_ + t_blk) * D_;
        Bgh = envT_h + ((size_t)h * NN_ + n_blk) * D_;
        Bgl = envT_l + ((size_t)h * NN_ + n_blk) * D_;
    }
    ZERO_ACC
    gemm_bf16(Agh, Agl, D_, Bgh, Bgl, D_, D_, smem_u32(smd), acc, tid, lane, wm, wn);

    const size_t hbase = (size_t)h * T_ * NN_;
    #pragma unroll
    for (int mi = 0; mi < 4; mi++)
        #pragma unroll
        for (int ni = 0; ni < 4; ni++) {
            int C0 = n_blk + wn + ni * 8 + 2 * tig;   // always even
            #pragma unroll
            for (int hh = 0; hh < 2; hh++) {
                int t = t_blk + wm + mi * 16 + grp + 8 * hh;
                float v0 = fmaxf(acc[mi][ni][2 * hh], 0.f);
                float v1 = fmaxf(acc[mi][ni][2 * hh + 1], 0.f);
                size_t rb = hbase + (size_t)t * NN_ + C0;
                if (MODE == 1) {
                    *reinterpret_cast<float2*>(&g_xs[rb]) = make_float2(v0, v1);
                    size_t pb = (size_t)t * (NN_ / 2) + (C0 >> 1);
                    float pcv = g_pc[pb];
                    float psv = g_ps[pb];
                    float q0 = v0 * pcv - v1 * psv;
                    float q1 = v1 * pcv + v0 * psv;
                    st_split2(qr_h, qr_l, rb, q0, q1);
                } else {
                    float2 xs = *reinterpret_cast<const float2*>(&g_xs[rb]);
                    st_split2(qr_h, qr_l, rb, v0 * xs.x, v1 * xs.y);
                }
            }
        }
}

// ---------------- scores = tril(qr @ qr^T, k=-1); compact triangular grid -------------
__global__ void __launch_bounds__(256, 2) k_scores() {
    // decode (bx, by) with bx <= by from linear triangular index
    int q = blockIdx.x;
    int by = (int)((sqrtf(8.0f * q + 1.0f) - 1.0f) * 0.5f);
    while ((by + 1) * (by + 2) / 2 <= q) by++;
    while (by * (by + 1) / 2 > q) by--;
    int bx = q - by * (by + 1) / 2;
    const int hz = blockIdx.y;

    extern __shared__ uint32_t smd[];
    WARP_IDS
    const bf16* Agh = qr_h + ((size_t)hz * T_ + by * 128) * NN_;
    const bf16* Agl = qr_l + ((size_t)hz * T_ + by * 128) * NN_;
    const bf16* Bgh = qr_h + ((size_t)hz * T_ + bx * 128) * NN_;
    const bf16* Bgl = qr_l + ((size_t)hz * T_ + bx * 128) * NN_;
    ZERO_ACC
    gemm_bf16(Agh, Agl, NN_, Bgh, Bgl, NN_, NN_, smem_u32(smd), acc, tid, lane, wm, wn);

    const size_t hbase = (size_t)hz * T_ * T_;
    int t_blk = by * 128, u_blk = bx * 128;
    if (bx != by) {
        #pragma unroll
        for (int mi = 0; mi < 4; mi++)
            #pragma unroll
            for (int ni = 0; ni < 4; ni++) {
                int C0 = u_blk + wn + ni * 8 + 2 * tig;
                #pragma unroll
                for (int h2 = 0; h2 < 2; h2++) {
                    int t = t_blk + wm + mi * 16 + grp + 8 * h2;
                    st_split2(sc_h, sc_l, hbase + (size_t)t * T_ + C0,
                              acc[mi][ni][2 * h2], acc[mi][ni][2 * h2 + 1]);
                }
            }
    } else {
        #pragma unroll
        for (int mi = 0; mi < 4; mi++)
            #pragma unroll
            for (int ni = 0; ni < 4; ni++) {
                int C0 = u_blk + wn + ni * 8 + 2 * tig;
                #pragma unroll
                for (int h2 = 0; h2 < 2; h2++) {
                    int t = t_blk + wm + mi * 16 + grp + 8 * h2;
                    float v0 = (C0     < t) ? acc[mi][ni][2 * h2]     : 0.f;
                    float v1 = (C0 + 1 < t) ? acc[mi][ni][2 * h2 + 1] : 0.f;
                    st_split2(sc_h, sc_l, hbase + (size_t)t * T_ + C0, v0, v1);
                }
            }
    }
}

// ---------------- yKV_raw = scores @ x, split-K=2 into g_part -------------------------
__global__ void __launch_bounds__(256, 2) k_ykv() {
    extern __shared__ uint32_t smd[];
    WARP_IDS
    const int h   = blockIdx.z >> 1;
    const int seg = blockIdx.z & 1;
    const int by  = blockIdx.y;
    const int Kend = (by + 1) * 128;
    const int Khalf = (by + 1) * 64;          // multiple of 64 -> NT multiple of 4
    const int k0 = seg ? Khalf : 0;
    const int Kseg = seg ? (Kend - Khalf) : Khalf;
    const bf16* Agh = sc_h + ((size_t)h * T_ + by * 128) * T_ + k0;
    const bf16* Agl = sc_l + ((size_t)h * T_ + by * 128) * T_ + k0;
    const bf16* Bgh = xT_h + (size_t)blockIdx.x * 128 * T_ + k0;
    const bf16* Bgl = xT_l + (size_t)blockIdx.x * 128 * T_ + k0;
    ZERO_ACC
    gemm_bf16(Agh, Agl, T_, Bgh, Bgl, T_, Kseg, smem_u32(smd), acc, tid, lane, wm, wn);
    store_plain(g_part + (size_t)(h * 2 + seg) * T_ * D_, D_, by * 128, blockIdx.x * 128,
                acc, wm, wn, grp, tig);
}

// ---------------- LN(sum of ykv partials) -> planes ----------------
__global__ void k_ln_ykv() {
    size_t r = blockIdx.x;                 // r = h*T + t
    int h = (int)(r / T_);
    int t = (int)(r % T_);
    int d = threadIdx.x;
    size_t o = (size_t)t * D_ + d;
    float v = g_part[(size_t)(h * 2) * T_ * D_ + o] + g_part[(size_t)(h * 2 + 1) * T_ * D_ + o];
    float m   = blk_sum256(v) * (1.0f / D_);
    float dv  = v - m;
    float var = blk_sum256(dv * dv) * (1.0f / D_);
    float y = dv * rsqrtf(var + EPS_);
    bf16 hb = __float2bfloat16(y);
    yp_h[r * D_ + d] = hb;
    yp_l[r * D_ + d] = __float2bfloat16(y - __bfloat162float(hb));
}

// ---------------- decoder GEMM, split-K=8 ----------------
__global__ void __launch_bounds__(256, 2) k_dec() {
    extern __shared__ uint32_t smd[];
    WARP_IDS
    const int seg = blockIdx.z;
    const int h = seg >> 1;
    const int colb = (seg & 1) * 1024;
    const int t_blk = blockIdx.y * 128, c_blk = blockIdx.x * 128;
    const bf16* Agh = qr_h + ((size_t)h * T_ + t_blk) * NN_ + colb;
    const bf16* Agl = qr_l + ((size_t)h * T_ + t_blk) * NN_ + colb;
    const bf16* Bgh = decT_h + (size_t)c_blk * NHN_ + seg * 1024;
    const bf16* Bgl = decT_l + (size_t)c_blk * NHN_ + seg * 1024;
    ZERO_ACC
    gemm_bf16(Agh, Agl, NN_, Bgh, Bgl, NHN_, 1024, smem_u32(smd), acc, tid, lane, wm, wn);
    store_plain(g_part + (size_t)seg * T_ * D_, D_, t_blk, c_blk, acc, wm, wn, grp, tig);
}

// ---------------- x = LN(x + LN(sum_partials)); refresh planes ----------------
__global__ void k_ln2() {
    int t = blockIdx.x, d = threadIdx.x;
    size_t o = (size_t)t * D_ + d;
    float y = 0.f;
    #pragma unroll
    for (int s = 0; s < 8; s++) y += g_part[(size_t)s * T_ * D_ + o];
    float m1 = blk_sum256(y) * (1.0f / D_);
    float dy = y - m1;
    float v1 = blk_sum256(dy * dy) * (1.0f / D_);
    float u  = dy * rsqrtf(v1 + EPS_);
    float w  = g_x[o] + u;
    float m2 = blk_sum256(w) * (1.0f / D_);
    float dw = w - m2;
    float v2 = blk_sum256(dw * dw) * (1.0f / D_);
    float x  = dw * rsqrtf(v2 + EPS_);
    g_x[o] = x;
    bf16 h = __float2bfloat16(x);
    bf16 l = __float2bfloat16(x - __bfloat162float(h));
    xp_h[o] = h; xp_l[o] = l;
    size_t ot = (size_t)d * T_ + t;
    xT_h[ot] = h; xT_l[ot] = l;
}

// ---------------- logits = x @ lm_head ----------------
__global__ void __launch_bounds__(256, 2) k_logits(float* __restrict__ out) {
    extern __shared__ uint32_t smd[];
    WARP_IDS
    const int t_blk = blockIdx.y * 128, c_blk = blockIdx.x * 128;
    const bf16* Agh = xp_h + (size_t)t_blk * D_;
    const bf16* Agl = xp_l + (size_t)t_blk * D_;
    const bf16* Bgh = lmhT_h + (size_t)c_blk * D_;
    const bf16* Bgl = lmhT_l + (size_t)c_blk * D_;
    ZERO_ACC
    gemm_bf16(Agh, Agl, D_, Bgh, Bgl, D_, D_, smem_u32(smd), acc, tid, lane, wm, wn);
    store_plain(out, VOCAB_, t_blk, c_blk, acc, wm, wn, grp, tig);
}

// ---------------- host launch ----------------
extern "C" void kernel_launch(void* const* d_in, const int* in_sizes, int n_in,
                              void* d_out, int out_size) {
    (void)in_sizes; (void)n_in; (void)out_size;
    const int*   idx   = (const int*)d_in[0];
    const float* embed = (const float*)d_in[1];
    const float* enc   = (const float*)d_in[2];
    const float* encv  = (const float*)d_in[3];
    const float* dec   = (const float*)d_in[4];
    const float* lmh   = (const float*)d_in[5];
    float* out = (float*)d_out;

    cudaFuncSetAttribute(k_enc<1>, cudaFuncAttributeMaxDynamicSharedMemorySize, SMEM_DYN);
    cudaFuncSetAttribute(k_enc<4>, cudaFuncAttributeMaxDynamicSharedMemorySize, SMEM_DYN);
    cudaFuncSetAttribute(k_scores, cudaFuncAttributeMaxDynamicSharedMemorySize, SMEM_DYN);
    cudaFuncSetAttribute(k_ykv,    cudaFuncAttributeMaxDynamicSharedMemorySize, SMEM_DYN);
    cudaFuncSetAttribute(k_dec,    cudaFuncAttributeMaxDynamicSharedMemorySize, SMEM_DYN);
    cudaFuncSetAttribute(k_logits, cudaFuncAttributeMaxDynamicSharedMemorySize, SMEM_DYN);

    bf16 *p_encT_h, *p_encT_l, *p_envT_h, *p_envT_l, *p_decT_h, *p_decT_l, *p_lmhT_h, *p_lmhT_l;
    cudaGetSymbolAddress((void**)&p_encT_h, encT_h);
    cudaGetSymbolAddress((void**)&p_encT_l, encT_l);
    cudaGetSymbolAddress((void**)&p_envT_h, envT_h);
    cudaGetSymbolAddress((void**)&p_envT_l, envT_l);
    cudaGetSymbolAddress((void**)&p_decT_h, decT_h);
    cudaGetSymbolAddress((void**)&p_decT_l, decT_l);
    cudaGetSymbolAddress((void**)&p_lmhT_h, lmhT_h);
    cudaGetSymbolAddress((void**)&p_lmhT_l, lmhT_l);

    dim3 tb(32, 8);
    k_rope_tab<<<T_, 256>>>();
    k_tsplit<<<dim3(NN_ / 32, D_ / 32, NH_), tb>>>(enc,  p_encT_h, p_encT_l, D_, NN_);
    k_tsplit<<<dim3(NN_ / 32, D_ / 32, NH_), tb>>>(encv, p_envT_h, p_envT_l, D_, NN_);
    k_tsplit<<<dim3(D_ / 32, NHN_ / 32, 1), tb>>>(dec,  p_decT_h, p_decT_l, NHN_, D_);
    k_tsplit<<<dim3(VOCAB_ / 32, D_ / 32, 1), tb>>>(lmh, p_lmhT_h, p_lmhT_l, D_, VOCAB_);
    k_embed_ln<<<T_, 256>>>(idx, embed);

    for (int l = 0; l < NL_; ++l) {
        k_enc<1><<<dim3(16, 16, NH_), 256, SMEM_DYN>>>();
        k_scores<<<dim3(136, NH_, 1), 256, SMEM_DYN>>>();
        k_ykv<<<dim3(2, 16, NH_ * 2), 256, SMEM_DYN>>>();
        k_ln_ykv<<<NH_ * T_, 256>>>();
        k_enc<4><<<dim3(16, 16, NH_), 256, SMEM_DYN>>>();
        k_dec<<<dim3(2, 16, 8), 256, SMEM_DYN>>>();
        k_ln2<<<T_, 256>>>();
    }
    k_logits<<<dim3(2, 16, 1), 256, SMEM_DYN>>>(out);
}